// round 2
// baseline (speedup 1.0000x reference)
#include <cuda_runtime.h>
#include <math.h>
#include <stdint.h>

// Problem constants
#define CIN    512
#define COUT1  1024
#define SSP    32            // spatial size
#define NBATCH 32
#define K1     4608          // CIN*9
#define MTOT   32768         // NBATCH*SSP*SSP
#define COUT2  425
#define N2PAD  512
#define K2     1024

// Scratch (static device memory; no runtime allocation)
__device__ float g_wT1[(size_t)K1 * COUT1];     // conv1 weights, [k][n], BN scale folded
__device__ float g_xT [(size_t)COUT1 * MTOT];   // conv1 output (post BN+leaky), [c][m]
__device__ float g_wT2[(size_t)K2 * N2PAD];     // conv2 weights, [k][n], zero padded n>=425
__device__ float g_p  [(size_t)MTOT * COUT2];   // conv2 output, [m][n]

__constant__ float c_anc_w[5] = {42.f, 98.f, 180.f, 300.f, 400.f};
__constant__ float c_anc_h[5] = {45.f, 130.f, 260.f, 180.f, 400.f};

// ---------------------------------------------------------------------------
// Weight transpose + BN fold (tiny, once per launch)
// ---------------------------------------------------------------------------
__global__ void k_transpose1(const float* __restrict__ w,
                             const float* __restrict__ gma,
                             const float* __restrict__ var) {
    __shared__ float tile[32][33];
    int kb = blockIdx.x * 32, nb = blockIdx.y * 32;
    int txd = threadIdx.x, tyd = threadIdx.y;
#pragma unroll
    for (int r = 0; r < 4; r++) {
        int n = nb + tyd + r * 8;
        tile[tyd + r * 8][txd] = w[(size_t)n * K1 + kb + txd];
    }
    __syncthreads();
    int n = nb + txd;
    float scale = gma[n] / sqrtf(var[n] + 1e-5f);
#pragma unroll
    for (int r = 0; r < 4; r++) {
        int k = kb + tyd + r * 8;
        g_wT1[(size_t)k * COUT1 + n] = tile[txd][tyd + r * 8] * scale;
    }
}

__global__ void k_transpose2(const float* __restrict__ w) {
    __shared__ float tile[32][33];
    int kb = blockIdx.x * 32, nb = blockIdx.y * 32;
    int txd = threadIdx.x, tyd = threadIdx.y;
#pragma unroll
    for (int r = 0; r < 4; r++) {
        int n = nb + tyd + r * 8;
        tile[tyd + r * 8][txd] = (n < COUT2) ? w[(size_t)n * K2 + kb + txd] : 0.0f;
    }
    __syncthreads();
    int n = nb + txd;
#pragma unroll
    for (int r = 0; r < 4; r++) {
        int k = kb + tyd + r * 8;
        g_wT2[(size_t)k * N2PAD + n] = tile[txd][tyd + r * 8];
    }
}

// ---------------------------------------------------------------------------
// Conv1: implicit GEMM  M=32768, N=1024, K=4608 (+ BN bias + leaky ReLU)
// Output stored transposed: g_xT[n][m]
// ---------------------------------------------------------------------------
__global__ __launch_bounds__(256, 2)
void k_conv1(const float* __restrict__ feat,
             const float* __restrict__ gma, const float* __restrict__ bet,
             const float* __restrict__ mea, const float* __restrict__ var) {
    __shared__ __align__(16) float As[2][16][128];
    __shared__ __align__(16) float Bs[2][16][128];

    const int tid = threadIdx.x;
    const int txc = tid & 15, tyc = tid >> 4;
    const int m0 = blockIdx.x * 128;
    const int n0 = blockIdx.y * 128;
    const int bimg = m0 >> 10;       // 128 | 1024 -> whole tile in one image
    const int pos0 = m0 & 1023;

    // A loader: each thread owns fixed (am, y, x); ak = akbase + 2*j
    const int am = tid & 127;
    const int akbase = tid >> 7;     // 0 or 1
    const int pos = pos0 + am;
    const int ay = pos >> 5, ax = pos & 31;

    // B loader: float4 along n
    const int bn = (tid & 31) * 4;
    const int bkbase = tid >> 5;     // 0..7

    float acc[8][8];
#pragma unroll
    for (int i = 0; i < 8; i++)
#pragma unroll
        for (int j = 0; j < 8; j++) acc[i][j] = 0.f;

    float  ldA[8];
    float4 ldB[2];

    const int nk = K1 / 16;

    // prologue load (kt = 0)
    {
        const int k0 = 0;
#pragma unroll
        for (int j = 0; j < 8; j++) {
            int kk = k0 + akbase + 2 * j;
            int c = kk / 9;
            int q = kk - 9 * c;
            int r = q / 3;
            int iy = ay + r - 1;
            int ix = ax + (q - 3 * r) - 1;
            float v = 0.f;
            if ((unsigned)iy < 32u && (unsigned)ix < 32u)
                v = feat[(((size_t)bimg * CIN + c) << 10) + (iy << 5) + ix];
            ldA[j] = v;
        }
#pragma unroll
        for (int j = 0; j < 2; j++)
            ldB[j] = *reinterpret_cast<const float4*>(
                &g_wT1[(size_t)(k0 + bkbase + 8 * j) * COUT1 + n0 + bn]);
#pragma unroll
        for (int j = 0; j < 8; j++) As[0][akbase + 2 * j][am] = ldA[j];
#pragma unroll
        for (int j = 0; j < 2; j++)
            *reinterpret_cast<float4*>(&Bs[0][bkbase + 8 * j][bn]) = ldB[j];
    }
    __syncthreads();

    for (int kt = 0; kt < nk; kt++) {
        const int cur = kt & 1;
        if (kt + 1 < nk) {
            const int k0 = (kt + 1) * 16;
#pragma unroll
            for (int j = 0; j < 8; j++) {
                int kk = k0 + akbase + 2 * j;
                int c = kk / 9;
                int q = kk - 9 * c;
                int r = q / 3;
                int iy = ay + r - 1;
                int ix = ax + (q - 3 * r) - 1;
                float v = 0.f;
                if ((unsigned)iy < 32u && (unsigned)ix < 32u)
                    v = feat[(((size_t)bimg * CIN + c) << 10) + (iy << 5) + ix];
                ldA[j] = v;
            }
#pragma unroll
            for (int j = 0; j < 2; j++)
                ldB[j] = *reinterpret_cast<const float4*>(
                    &g_wT1[(size_t)(k0 + bkbase + 8 * j) * COUT1 + n0 + bn]);
        }
#pragma unroll
        for (int dk = 0; dk < 16; dk++) {
            float4 a0 = *reinterpret_cast<const float4*>(&As[cur][dk][tyc * 8]);
            float4 a1 = *reinterpret_cast<const float4*>(&As[cur][dk][tyc * 8 + 4]);
            float4 b0 = *reinterpret_cast<const float4*>(&Bs[cur][dk][txc * 8]);
            float4 b1 = *reinterpret_cast<const float4*>(&Bs[cur][dk][txc * 8 + 4]);
            float a[8] = {a0.x, a0.y, a0.z, a0.w, a1.x, a1.y, a1.z, a1.w};
            float b[8] = {b0.x, b0.y, b0.z, b0.w, b1.x, b1.y, b1.z, b1.w};
#pragma unroll
            for (int i = 0; i < 8; i++)
#pragma unroll
                for (int j = 0; j < 8; j++)
                    acc[i][j] = fmaf(a[i], b[j], acc[i][j]);
        }
        if (kt + 1 < nk) {
            const int nxt = cur ^ 1;
#pragma unroll
            for (int j = 0; j < 8; j++) As[nxt][akbase + 2 * j][am] = ldA[j];
#pragma unroll
            for (int j = 0; j < 2; j++)
                *reinterpret_cast<float4*>(&Bs[nxt][bkbase + 8 * j][bn]) = ldB[j];
        }
        __syncthreads();
    }

    // Epilogue: BN bias + leaky, store transposed [n][m]
#pragma unroll
    for (int jj = 0; jj < 8; jj++) {
        int n = n0 + txc * 8 + jj;
        float scale = gma[n] / sqrtf(var[n] + 1e-5f);
        float bias = bet[n] - mea[n] * scale;
        size_t rowbase = (size_t)n * MTOT + m0 + tyc * 8;
        float4 v0, v1;
        float t;
        t = acc[0][jj] + bias; v0.x = t > 0.f ? t : 0.1f * t;
        t = acc[1][jj] + bias; v0.y = t > 0.f ? t : 0.1f * t;
        t = acc[2][jj] + bias; v0.z = t > 0.f ? t : 0.1f * t;
        t = acc[3][jj] + bias; v0.w = t > 0.f ? t : 0.1f * t;
        t = acc[4][jj] + bias; v1.x = t > 0.f ? t : 0.1f * t;
        t = acc[5][jj] + bias; v1.y = t > 0.f ? t : 0.1f * t;
        t = acc[6][jj] + bias; v1.z = t > 0.f ? t : 0.1f * t;
        t = acc[7][jj] + bias; v1.w = t > 0.f ? t : 0.1f * t;
        *reinterpret_cast<float4*>(&g_xT[rowbase])     = v0;
        *reinterpret_cast<float4*>(&g_xT[rowbase + 4]) = v1;
    }
}

// ---------------------------------------------------------------------------
// Conv2: GEMM  M=32768, N=512(pad of 425), K=1024 (+ bias). Output g_p[m][n].
// ---------------------------------------------------------------------------
__global__ __launch_bounds__(256, 2)
void k_conv2(const float* __restrict__ bias2) {
    __shared__ __align__(16) float As[2][16][128];
    __shared__ __align__(16) float Bs[2][16][128];

    const int tid = threadIdx.x;
    const int txc = tid & 15, tyc = tid >> 4;
    const int m0 = blockIdx.x * 128;
    const int n0 = blockIdx.y * 128;

    const int am4 = (tid & 31) * 4;
    const int akbase = tid >> 5;     // 0..7
    const int bn = (tid & 31) * 4;
    const int bkbase = tid >> 5;

    float acc[8][8];
#pragma unroll
    for (int i = 0; i < 8; i++)
#pragma unroll
        for (int j = 0; j < 8; j++) acc[i][j] = 0.f;

    float4 ldA[2], ldB[2];
    const int nk = K2 / 16;

    {
#pragma unroll
        for (int j = 0; j < 2; j++) {
            ldA[j] = *reinterpret_cast<const float4*>(
                &g_xT[(size_t)(akbase + 8 * j) * MTOT + m0 + am4]);
            ldB[j] = *reinterpret_cast<const float4*>(
                &g_wT2[(size_t)(bkbase + 8 * j) * N2PAD + n0 + bn]);
        }
#pragma unroll
        for (int j = 0; j < 2; j++) {
            *reinterpret_cast<float4*>(&As[0][akbase + 8 * j][am4]) = ldA[j];
            *reinterpret_cast<float4*>(&Bs[0][bkbase + 8 * j][bn]) = ldB[j];
        }
    }
    __syncthreads();

    for (int kt = 0; kt < nk; kt++) {
        const int cur = kt & 1;
        if (kt + 1 < nk) {
            const int k0 = (kt + 1) * 16;
#pragma unroll
            for (int j = 0; j < 2; j++) {
                ldA[j] = *reinterpret_cast<const float4*>(
                    &g_xT[(size_t)(k0 + akbase + 8 * j) * MTOT + m0 + am4]);
                ldB[j] = *reinterpret_cast<const float4*>(
                    &g_wT2[(size_t)(k0 + bkbase + 8 * j) * N2PAD + n0 + bn]);
            }
        }
#pragma unroll
        for (int dk = 0; dk < 16; dk++) {
            float4 a0 = *reinterpret_cast<const float4*>(&As[cur][dk][tyc * 8]);
            float4 a1 = *reinterpret_cast<const float4*>(&As[cur][dk][tyc * 8 + 4]);
            float4 b0 = *reinterpret_cast<const float4*>(&Bs[cur][dk][txc * 8]);
            float4 b1 = *reinterpret_cast<const float4*>(&Bs[cur][dk][txc * 8 + 4]);
            float a[8] = {a0.x, a0.y, a0.z, a0.w, a1.x, a1.y, a1.z, a1.w};
            float b[8] = {b0.x, b0.y, b0.z, b0.w, b1.x, b1.y, b1.z, b1.w};
#pragma unroll
            for (int i = 0; i < 8; i++)
#pragma unroll
                for (int j = 0; j < 8; j++)
                    acc[i][j] = fmaf(a[i], b[j], acc[i][j]);
        }
        if (kt + 1 < nk) {
            const int nxt = cur ^ 1;
#pragma unroll
            for (int j = 0; j < 2; j++) {
                *reinterpret_cast<float4*>(&As[nxt][akbase + 8 * j][am4]) = ldA[j];
                *reinterpret_cast<float4*>(&Bs[nxt][bkbase + 8 * j][bn]) = ldB[j];
            }
        }
        __syncthreads();
    }

#pragma unroll
    for (int jj = 0; jj < 8; jj++) {
        int n = n0 + txc * 8 + jj;
        if (n < COUT2) {
            float bz = bias2[n];
#pragma unroll
            for (int i = 0; i < 8; i++) {
                int m = m0 + tyc * 8 + i;
                g_p[(size_t)m * COUT2 + n] = acc[i][jj] + bz;
            }
        }
    }
}

// ---------------------------------------------------------------------------
// Decode: one warp per (position, anchor)
// out layout: out5 [32][5120][5] f32 then labels [32][5120] as f32
// ---------------------------------------------------------------------------
__global__ void k_decode(float* __restrict__ out) {
    int g = blockIdx.x * (blockDim.x >> 5) + (threadIdx.x >> 5);
    int lane = threadIdx.x & 31;
    if (g >= MTOT * 5) return;
    int m = g / 5;
    int a = g - m * 5;
    const float* base = g_p + (size_t)m * COUT2 + a * 85;

    float t0 = base[0], t1 = base[1], t2 = base[2], t3 = base[3], t4 = base[4];

    float l0 = base[5 + lane];
    float l1 = base[5 + 32 + lane];
    float best = l0; int bi = lane;
    if (l1 > best) { best = l1; bi = lane + 32; }
    float l2 = -3.4e38f;
    if (lane < 16) {
        l2 = base[5 + 64 + lane];
        if (l2 > best) { best = l2; bi = lane + 64; }
    }
#pragma unroll
    for (int off = 16; off; off >>= 1) {
        float ob = __shfl_down_sync(0xffffffffu, best, off);
        int   oi = __shfl_down_sync(0xffffffffu, bi, off);
        if (ob > best || (ob == best && oi < bi)) { best = ob; bi = oi; }
    }
    float mx = __shfl_sync(0xffffffffu, best, 0);
    int gidx = __shfl_sync(0xffffffffu, bi, 0);

    float s = expf(l0 - mx) + expf(l1 - mx) + ((lane < 16) ? expf(l2 - mx) : 0.f);
#pragma unroll
    for (int off = 16; off; off >>= 1)
        s += __shfl_down_sync(0xffffffffu, s, off);

    if (lane == 0) {
        float bx = 1.f / (1.f + expf(-t0));
        float by = 1.f / (1.f + expf(-t1));
        float bw = expf(fminf(t2, 8.f));
        float bh = expf(fminf(t3, 8.f));
        float obj = 1.f / (1.f + expf(-t4));
        float score = obj / s;                  // max softmax = 1/sum(exp(l - max))

        int b = m >> 10;
        int pos = m & 1023;
        int gy = pos >> 5, gx = pos & 31;
        float cx = (bx + (float)gx) * 32.f;
        float cy = (by + (float)gy) * 32.f;
        float pw = c_anc_w[a] * bw;             // (anchor/32)*bw*32 == anchor*bw (exact)
        float ph = c_anc_h[a] * bh;
        float x1 = fminf(fmaxf(cx - 0.5f * pw, 0.f), 1023.f);
        float y1 = fminf(fmaxf(cy - 0.5f * ph, 0.f), 1023.f);
        float x2 = fminf(fmaxf(cx + 0.5f * pw, 0.f), 1023.f);
        float y2 = fminf(fmaxf(cy + 0.5f * ph, 0.f), 1023.f);

        int idxo = pos * 5 + a;                 // (y, x, anchor) flattened
        float* o5 = out + ((size_t)b * 5120 + idxo) * 5;
        o5[0] = x1; o5[1] = y1; o5[2] = x2; o5[3] = y2; o5[4] = score;
        out[(size_t)NBATCH * 5120 * 5 + (size_t)b * 5120 + idxo] = (float)gidx;
    }
}

// ---------------------------------------------------------------------------
extern "C" void kernel_launch(void* const* d_in, const int* in_sizes, int n_in,
                              void* d_out, int out_size) {
    const float* feat = (const float*)d_in[0];
    const float* w1   = (const float*)d_in[1];
    const float* gma  = (const float*)d_in[2];
    const float* bet  = (const float*)d_in[3];
    const float* mea  = (const float*)d_in[4];
    const float* var  = (const float*)d_in[5];
    const float* w2   = (const float*)d_in[6];
    const float* b2   = (const float*)d_in[7];
    float* out = (float*)d_out;

    k_transpose1<<<dim3(K1 / 32, COUT1 / 32), dim3(32, 8)>>>(w1, gma, var);
    k_transpose2<<<dim3(K2 / 32, N2PAD / 32), dim3(32, 8)>>>(w2);
    k_conv1<<<dim3(MTOT / 128, COUT1 / 128), 256>>>(feat, gma, bet, mea, var);
    k_conv2<<<dim3(MTOT / 128, N2PAD / 128), 256>>>(b2);
    k_decode<<<(MTOT * 5 * 32 + 255) / 256, 256>>>(out);
}

// round 4
// speedup vs baseline: 1.5314x; 1.5314x over previous
#include <cuda_runtime.h>
#include <cuda_bf16.h>
#include <mma.h>
#include <math.h>
#include <stdint.h>

using namespace nvcuda;

// Problem constants
#define CIN    512
#define COUT1  1024
#define NBATCH 32
#define K1     4608          // CIN*9
#define MTOT   32768         // NBATCH*32*32
#define COUT2  425
#define N2PAD  512
#define K2     1024

// conv1/conv2 wmma tiling
#define KC     32
#define NKT1   (K1 / KC)     // 144
#define NKT2   (K2 / KC)     // 32

// conv1 smem: 4 matrices [128][40] bf16 per stage, 2 stages
#define SA1        40
#define C1_AHI     0
#define C1_ALO     5120
#define C1_BHI     10240
#define C1_BLO     15360
#define C1_STAGE   20480                  // elements
#define C1_SMEM_B  (2 * C1_STAGE * 2)     // 81920 bytes

// conv2 smem: 4 matrices [32][136] bf16 per stage, 2 stages
#define SA2        136
#define C2_AHI     0
#define C2_ALO     4352
#define C2_BHI     8704
#define C2_BLO     13056
#define C2_STAGE   17408                  // elements
#define C2_SMEM_B  (2 * C2_STAGE * 2)     // 69632 bytes

// Scratch (static device memory; no runtime allocation)
__device__ __align__(16) __nv_bfloat16 g_w1hi[(size_t)COUT1 * K1]; // [n][k]
__device__ __align__(16) __nv_bfloat16 g_w1lo[(size_t)COUT1 * K1];
__device__ __align__(16) __nv_bfloat16 g_xhi[(size_t)COUT1 * MTOT]; // [k][m]
__device__ __align__(16) __nv_bfloat16 g_xlo[(size_t)COUT1 * MTOT];
__device__ __align__(16) __nv_bfloat16 g_w2hi[(size_t)K2 * N2PAD];  // [k][n]
__device__ __align__(16) __nv_bfloat16 g_w2lo[(size_t)K2 * N2PAD];
__device__ float g_p[(size_t)MTOT * COUT2];                         // [m][n]

__constant__ float c_anc_w[5] = {42.f, 98.f, 180.f, 300.f, 400.f};
__constant__ float c_anc_h[5] = {45.f, 130.f, 260.f, 180.f, 400.f};

__device__ __forceinline__ void split_bf16(float v, unsigned short& h, unsigned short& l) {
    __nv_bfloat16 hb = __float2bfloat16_rn(v);
    h = __bfloat16_as_ushort(hb);
    l = __bfloat16_as_ushort(__float2bfloat16_rn(v - __bfloat162float(hb)));
}

// ---------------------------------------------------------------------------
// Weight prep
// ---------------------------------------------------------------------------
__global__ void k_split_w1(const float* __restrict__ w,
                           const float* __restrict__ gma,
                           const float* __restrict__ var) {
    int idx = blockIdx.x * 256 + threadIdx.x;
    if (idx >= COUT1 * K1) return;
    int n = idx / K1;
    float scale = gma[n] * rsqrtf(var[n] + 1e-5f);
    float v = w[idx] * scale;
    unsigned short h, l;
    split_bf16(v, h, l);
    g_w1hi[idx] = __ushort_as_bfloat16(h);
    g_w1lo[idx] = __ushort_as_bfloat16(l);
}

__global__ void k_split_w2(const float* __restrict__ w) {
    __shared__ float tile[32][33];
    int kb = blockIdx.x * 32, nb = blockIdx.y * 32;
    int txd = threadIdx.x, tyd = threadIdx.y;
#pragma unroll
    for (int r = 0; r < 4; r++) {
        int n = nb + tyd + r * 8;
        tile[tyd + r * 8][txd] = (n < COUT2) ? w[(size_t)n * K2 + kb + txd] : 0.0f;
    }
    __syncthreads();
    int n = nb + txd;
#pragma unroll
    for (int r = 0; r < 4; r++) {
        int k = kb + tyd + r * 8;
        unsigned short h, l;
        split_bf16(tile[txd][tyd + r * 8], h, l);
        g_w2hi[(size_t)k * N2PAD + n] = __ushort_as_bfloat16(h);
        g_w2lo[(size_t)k * N2PAD + n] = __ushort_as_bfloat16(l);
    }
}

// ---------------------------------------------------------------------------
// Conv1: wmma bf16x3 implicit GEMM. M=32768, N=1024, K=4608.
// CTA 128x128, 8 warps (4x2), warp 32x64. Epilogue: BN+leaky -> bf16 hi/lo [k][m]
// ---------------------------------------------------------------------------
__global__ __launch_bounds__(256)
void k_conv1_wm(const float* __restrict__ feat,
                const float* __restrict__ gma, const float* __restrict__ bet,
                const float* __restrict__ mea, const float* __restrict__ var) {
    extern __shared__ __align__(16) char smraw[];
    __nv_bfloat16* smb = (__nv_bfloat16*)smraw;
    float* smf = (float*)smraw;

    const int tid = threadIdx.x;
    const int w = tid >> 5;
    const int wm = w & 3, wn = w >> 2;
    const int m0 = blockIdx.x * 128;
    const int n0 = blockIdx.y * 128;

    // A loader geometry: row = tid>>1 (m within tile), kh = tid&1 (16-k half)
    const int arow = tid >> 1;
    const int ks = (tid & 1) * 16;
    const int m = m0 + arow;
    const int bimg = m >> 10;
    const int pos = m & 1023;
    const int ay = pos >> 5, ax = pos & 31;
    const float* fbase = feat + ((size_t)bimg * CIN << 10);

    // B loader: row n = tid>>1, same k half
    const int brow = tid >> 1;

    wmma::fragment<wmma::accumulator, 16, 16, 16, float> acc[2][4];
#pragma unroll
    for (int i = 0; i < 2; i++)
#pragma unroll
        for (int j = 0; j < 4; j++) wmma::fill_fragment(acc[i][j], 0.0f);

    float fa[16];
    uint4 bh[2], bl[2];

    // -- helpers as lambdas --
    auto gatherA = [&](int kc) {
#pragma unroll
        for (int j = 0; j < 16; j++) {
            int k = kc + ks + j;
            int c = k / 9;
            int q = k - 9 * c;
            int r = q / 3;
            int s = q - 3 * r;
            int iy = ay + r - 1, ix = ax + s - 1;
            float v = 0.f;
            if ((unsigned)iy < 32u && (unsigned)ix < 32u)
                v = fbase[(c << 10) + (iy << 5) + ix];
            fa[j] = v;
        }
    };
    auto loadB = [&](int kc) {
        const char* ph = (const char*)(g_w1hi + (size_t)(n0 + brow) * K1 + kc + ks);
        const char* pl = (const char*)(g_w1lo + (size_t)(n0 + brow) * K1 + kc + ks);
        bh[0] = *(const uint4*)ph; bh[1] = *(const uint4*)(ph + 16);
        bl[0] = *(const uint4*)pl; bl[1] = *(const uint4*)(pl + 16);
    };
    auto storeStage = [&](int st) {
        uint4 hv[2], lv[2];
        unsigned short* hp = (unsigned short*)hv;
        unsigned short* lp = (unsigned short*)lv;
#pragma unroll
        for (int j = 0; j < 16; j++) split_bf16(fa[j], hp[j], lp[j]);
        __nv_bfloat16* base = smb + st * C1_STAGE;
        int ao = arow * SA1 + ks;
        *(uint4*)(base + C1_AHI + ao) = hv[0];
        *(uint4*)(base + C1_AHI + ao + 8) = hv[1];
        *(uint4*)(base + C1_ALO + ao) = lv[0];
        *(uint4*)(base + C1_ALO + ao + 8) = lv[1];
        int bo = brow * SA1 + ks;
        *(uint4*)(base + C1_BHI + bo) = bh[0];
        *(uint4*)(base + C1_BHI + bo + 8) = bh[1];
        *(uint4*)(base + C1_BLO + bo) = bl[0];
        *(uint4*)(base + C1_BLO + bo + 8) = bl[1];
    };

    // prologue
    gatherA(0); loadB(0); storeStage(0);
    __syncthreads();

    for (int kt = 0; kt < NKT1; kt++) {
        const int cur = kt & 1;
        if (kt + 1 < NKT1) { gatherA((kt + 1) * KC); loadB((kt + 1) * KC); }

        const __nv_bfloat16* base = smb + cur * C1_STAGE;
#pragma unroll
        for (int term = 0; term < 3; term++) {
            const __nv_bfloat16* Ap = base + (term == 2 ? C1_ALO : C1_AHI);
            const __nv_bfloat16* Bp = base + (term == 1 ? C1_BLO : C1_BHI);
#pragma unroll
            for (int kk = 0; kk < KC; kk += 16) {
                wmma::fragment<wmma::matrix_a, 16, 16, 16, __nv_bfloat16, wmma::row_major> af[2];
                wmma::fragment<wmma::matrix_b, 16, 16, 16, __nv_bfloat16, wmma::col_major> bf[4];
#pragma unroll
                for (int i = 0; i < 2; i++)
                    wmma::load_matrix_sync(af[i], Ap + (wm * 32 + i * 16) * SA1 + kk, SA1);
#pragma unroll
                for (int j = 0; j < 4; j++)
                    wmma::load_matrix_sync(bf[j], Bp + (wn * 64 + j * 16) * SA1 + kk, SA1);
#pragma unroll
                for (int i = 0; i < 2; i++)
#pragma unroll
                    for (int j = 0; j < 4; j++)
                        wmma::mma_sync(acc[i][j], af[i], bf[j], acc[i][j]);
            }
        }
        if (kt + 1 < NKT1) storeStage(cur ^ 1);
        __syncthreads();
    }

    // Epilogue: acc -> smem col-major (element (m,n) at smf[n*128+m])
#pragma unroll
    for (int i = 0; i < 2; i++)
#pragma unroll
        for (int j = 0; j < 4; j++)
            wmma::store_matrix_sync(smf + (wn * 64 + j * 16) * 128 + wm * 32 + i * 16,
                                    acc[i][j], 128, wmma::mem_col_major);
    __syncthreads();

    // BN + leaky, split to bf16 hi/lo, store [k][m]
#pragma unroll
    for (int it = 0; it < 16; it++) {
        int id = it * 256 + tid;
        int ncol = id >> 5;
        int r4 = (id & 31) * 4;
        float4 v = *(const float4*)(smf + ncol * 128 + r4);
        int n = n0 + ncol;
        float scale = gma[n] * rsqrtf(var[n] + 1e-5f);
        float bias = bet[n] - mea[n] * scale;
        float t;
        unsigned short h[4], l[4];
        t = v.x + bias; t = t > 0.f ? t : 0.1f * t; split_bf16(t, h[0], l[0]);
        t = v.y + bias; t = t > 0.f ? t : 0.1f * t; split_bf16(t, h[1], l[1]);
        t = v.z + bias; t = t > 0.f ? t : 0.1f * t; split_bf16(t, h[2], l[2]);
        t = v.w + bias; t = t > 0.f ? t : 0.1f * t; split_bf16(t, h[3], l[3]);
        size_t go = (size_t)n * MTOT + m0 + r4;
        *(uint2*)(g_xhi + go) = *(const uint2*)h;
        *(uint2*)(g_xlo + go) = *(const uint2*)l;
    }
}

// ---------------------------------------------------------------------------
// Conv2: wmma bf16x3 GEMM. M=32768, N=512(pad of 425), K=1024 (+bias) -> g_p[m][n]
// ---------------------------------------------------------------------------
__global__ __launch_bounds__(256)
void k_conv2_wm(const float* __restrict__ bias2) {
    extern __shared__ __align__(16) char smraw[];
    __nv_bfloat16* smb = (__nv_bfloat16*)smraw;
    float* smf = (float*)smraw;

    const int tid = threadIdx.x;
    const int w = tid >> 5;
    const int wm = w & 3, wn = w >> 2;
    const int m0 = blockIdx.x * 128;
    const int n0 = blockIdx.y * 128;

    const int krow = tid >> 3;
    const int seg = (tid & 7) * 16;

    wmma::fragment<wmma::accumulator, 16, 16, 16, float> acc[2][4];
#pragma unroll
    for (int i = 0; i < 2; i++)
#pragma unroll
        for (int j = 0; j < 4; j++) wmma::fill_fragment(acc[i][j], 0.0f);

    uint4 ah[2], al[2], bh[2], bl[2];

    auto loadG = [&](int kc) {
        const char* p;
        p = (const char*)(g_xhi + (size_t)(kc + krow) * MTOT + m0 + seg);
        ah[0] = *(const uint4*)p; ah[1] = *(const uint4*)(p + 16);
        p = (const char*)(g_xlo + (size_t)(kc + krow) * MTOT + m0 + seg);
        al[0] = *(const uint4*)p; al[1] = *(const uint4*)(p + 16);
        p = (const char*)(g_w2hi + (size_t)(kc + krow) * N2PAD + n0 + seg);
        bh[0] = *(const uint4*)p; bh[1] = *(const uint4*)(p + 16);
        p = (const char*)(g_w2lo + (size_t)(kc + krow) * N2PAD + n0 + seg);
        bl[0] = *(const uint4*)p; bl[1] = *(const uint4*)(p + 16);
    };
    auto storeStage = [&](int st) {
        __nv_bfloat16* base = smb + st * C2_STAGE;
        int o = krow * SA2 + seg;
        *(uint4*)(base + C2_AHI + o) = ah[0]; *(uint4*)(base + C2_AHI + o + 8) = ah[1];
        *(uint4*)(base + C2_ALO + o) = al[0]; *(uint4*)(base + C2_ALO + o + 8) = al[1];
        *(uint4*)(base + C2_BHI + o) = bh[0]; *(uint4*)(base + C2_BHI + o + 8) = bh[1];
        *(uint4*)(base + C2_BLO + o) = bl[0]; *(uint4*)(base + C2_BLO + o + 8) = bl[1];
    };

    loadG(0); storeStage(0);
    __syncthreads();

    for (int kt = 0; kt < NKT2; kt++) {
        const int cur = kt & 1;
        if (kt + 1 < NKT2) loadG((kt + 1) * KC);

        const __nv_bfloat16* base = smb + cur * C2_STAGE;
#pragma unroll
        for (int term = 0; term < 3; term++) {
            const __nv_bfloat16* Ap = base + (term == 2 ? C2_ALO : C2_AHI);
            const __nv_bfloat16* Bp = base + (term == 1 ? C2_BLO : C2_BHI);
#pragma unroll
            for (int kk = 0; kk < KC; kk += 16) {
                wmma::fragment<wmma::matrix_a, 16, 16, 16, __nv_bfloat16, wmma::col_major> af[2];
                wmma::fragment<wmma::matrix_b, 16, 16, 16, __nv_bfloat16, wmma::row_major> bf[4];
#pragma unroll
                for (int i = 0; i < 2; i++)
                    wmma::load_matrix_sync(af[i], Ap + kk * SA2 + wm * 32 + i * 16, SA2);
#pragma unroll
                for (int j = 0; j < 4; j++)
                    wmma::load_matrix_sync(bf[j], Bp + kk * SA2 + wn * 64 + j * 16, SA2);
#pragma unroll
                for (int i = 0; i < 2; i++)
#pragma unroll
                    for (int j = 0; j < 4; j++)
                        wmma::mma_sync(acc[i][j], af[i], bf[j], acc[i][j]);
            }
        }
        if (kt + 1 < NKT2) storeStage(cur ^ 1);
        __syncthreads();
    }

    // Epilogue: acc -> smem row-major (element (m,n) at smf[m*128+n]), + bias -> g_p
#pragma unroll
    for (int i = 0; i < 2; i++)
#pragma unroll
        for (int j = 0; j < 4; j++)
            wmma::store_matrix_sync(smf + (wm * 32 + i * 16) * 128 + wn * 64 + j * 16,
                                    acc[i][j], 128, wmma::mem_row_major);
    __syncthreads();

#pragma unroll
    for (int it = 0; it < 16; it++) {
        int id = it * 256 + tid;
        int mrow = id >> 5;
        int nc4 = (id & 31) * 4;
        float4 v = *(const float4*)(smf + mrow * 128 + nc4);
        int n = n0 + nc4;
        float* dst = g_p + (size_t)(m0 + mrow) * COUT2 + n;
        if (n + 0 < COUT2) dst[0] = v.x + bias2[n + 0];
        if (n + 1 < COUT2) dst[1] = v.y + bias2[n + 1];
        if (n + 2 < COUT2) dst[2] = v.z + bias2[n + 2];
        if (n + 3 < COUT2) dst[3] = v.w + bias2[n + 3];
    }
}

// ---------------------------------------------------------------------------
// Decode: one warp per (position, anchor)
// out layout: out5 [32][5120][5] f32 then labels [32][5120] as f32
// ---------------------------------------------------------------------------
__global__ void k_decode(float* __restrict__ out) {
    int g = blockIdx.x * (blockDim.x >> 5) + (threadIdx.x >> 5);
    int lane = threadIdx.x & 31;
    if (g >= MTOT * 5) return;
    int m = g / 5;
    int a = g - m * 5;
    const float* base = g_p + (size_t)m * COUT2 + a * 85;

    float t0 = base[0], t1 = base[1], t2 = base[2], t3 = base[3], t4 = base[4];

    float l0 = base[5 + lane];
    float l1 = base[5 + 32 + lane];
    float best = l0; int bi = lane;
    if (l1 > best) { best = l1; bi = lane + 32; }
    float l2 = -3.4e38f;
    if (lane < 16) {
        l2 = base[5 + 64 + lane];
        if (l2 > best) { best = l2; bi = lane + 64; }
    }
#pragma unroll
    for (int off = 16; off; off >>= 1) {
        float ob = __shfl_down_sync(0xffffffffu, best, off);
        int   oi = __shfl_down_sync(0xffffffffu, bi, off);
        if (ob > best || (ob == best && oi < bi)) { best = ob; bi = oi; }
    }
    float mx = __shfl_sync(0xffffffffu, best, 0);
    int gidx = __shfl_sync(0xffffffffu, bi, 0);

    float s = expf(l0 - mx) + expf(l1 - mx) + ((lane < 16) ? expf(l2 - mx) : 0.f);
#pragma unroll
    for (int off = 16; off; off >>= 1)
        s += __shfl_down_sync(0xffffffffu, s, off);

    if (lane == 0) {
        float bx = 1.f / (1.f + expf(-t0));
        float by = 1.f / (1.f + expf(-t1));
        float bw = expf(fminf(t2, 8.f));
        float bh = expf(fminf(t3, 8.f));
        float obj = 1.f / (1.f + expf(-t4));
        float score = obj / s;

        int b = m >> 10;
        int pos = m & 1023;
        int gy = pos >> 5, gx = pos & 31;
        float cx = (bx + (float)gx) * 32.f;
        float cy = (by + (float)gy) * 32.f;
        float pw = c_anc_w[a] * bw;
        float ph = c_anc_h[a] * bh;
        float x1 = fminf(fmaxf(cx - 0.5f * pw, 0.f), 1023.f);
        float y1 = fminf(fmaxf(cy - 0.5f * ph, 0.f), 1023.f);
        float x2 = fminf(fmaxf(cx + 0.5f * pw, 0.f), 1023.f);
        float y2 = fminf(fmaxf(cy + 0.5f * ph, 0.f), 1023.f);

        int idxo = pos * 5 + a;
        float* o5 = out + ((size_t)b * 5120 + idxo) * 5;
        o5[0] = x1; o5[1] = y1; o5[2] = x2; o5[3] = y2; o5[4] = score;
        out[(size_t)NBATCH * 5120 * 5 + (size_t)b * 5120 + idxo] = (float)gidx;
    }
}

// ---------------------------------------------------------------------------
extern "C" void kernel_launch(void* const* d_in, const int* in_sizes, int n_in,
                              void* d_out, int out_size) {
    const float* feat = (const float*)d_in[0];
    const float* w1   = (const float*)d_in[1];
    const float* gma  = (const float*)d_in[2];
    const float* bet  = (const float*)d_in[3];
    const float* mea  = (const float*)d_in[4];
    const float* var  = (const float*)d_in[5];
    const float* w2   = (const float*)d_in[6];
    const float* b2   = (const float*)d_in[7];
    float* out = (float*)d_out;

    static int attr_set = 0;
    if (!attr_set) {
        cudaFuncSetAttribute(k_conv1_wm, cudaFuncAttributeMaxDynamicSharedMemorySize, C1_SMEM_B);
        cudaFuncSetAttribute(k_conv2_wm, cudaFuncAttributeMaxDynamicSharedMemorySize, C2_SMEM_B);
        attr_set = 1;
    }

    k_split_w1<<<(COUT1 * K1 + 255) / 256, 256>>>(w1, gma, var);
    k_split_w2<<<dim3(K2 / 32, N2PAD / 32), dim3(32, 8)>>>(w2);
    k_conv1_wm<<<dim3(MTOT / 128, COUT1 / 128), 256, C1_SMEM_B>>>(feat, gma, bet, mea, var);
    k_conv2_wm<<<dim3(MTOT / 128, N2PAD / 128), 256, C2_SMEM_B>>>(b2);
    k_decode<<<(MTOT * 5 * 32 + 255) / 256, 256>>>(out);
}

// round 5
// speedup vs baseline: 1.7342x; 1.1325x over previous
#include <cuda_runtime.h>
#include <cuda_bf16.h>
#include <mma.h>
#include <math.h>
#include <stdint.h>

using namespace nvcuda;

// Problem constants
#define CIN    512
#define COUT1  1024
#define NBATCH 32
#define K1     4608          // CIN*9
#define MTOT   32768         // NBATCH*32*32
#define COUT2  425
#define N2PAD  512
#define K2     1024

#define KC     32
#define NKT1   (K1 / KC)     // 144
#define NKT2   (K2 / KC)     // 32

// conv1 smem: 4 matrices [128][40] bf16 per stage, 2 stages
#define SA1        40
#define C1_AHI     0
#define C1_ALO     5120
#define C1_BHI     10240
#define C1_BLO     15360
#define C1_STAGE   20480
#define C1_SMEM_B  (2 * C1_STAGE * 2)     // 81920 bytes

// conv2 smem: 4 matrices [32][136] bf16 per stage, 2 stages
#define SA2        136
#define C2_AHI     0
#define C2_ALO     4352
#define C2_BHI     8704
#define C2_BLO     13056
#define C2_STAGE   17408
#define C2_SMEM_B  (2 * C2_STAGE * 2)     // 69632 bytes

// Scratch (static device memory)
__device__ __align__(16) __nv_bfloat16 g_w1hi[(size_t)COUT1 * K1]; // [n][k]
__device__ __align__(16) __nv_bfloat16 g_w1lo[(size_t)COUT1 * K1];
__device__ __align__(16) __nv_bfloat16 g_xhi[(size_t)COUT1 * MTOT]; // [k][m]
__device__ __align__(16) __nv_bfloat16 g_xlo[(size_t)COUT1 * MTOT];
__device__ __align__(16) __nv_bfloat16 g_w2hi[(size_t)K2 * N2PAD];  // [k][n]
__device__ __align__(16) __nv_bfloat16 g_w2lo[(size_t)K2 * N2PAD];
__device__ float g_p[(size_t)MTOT * COUT2];                         // [m][n]

__constant__ float c_anc_w[5] = {42.f, 98.f, 180.f, 300.f, 400.f};
__constant__ float c_anc_h[5] = {45.f, 130.f, 260.f, 180.f, 400.f};

__device__ __forceinline__ void split_bf16(float v, unsigned short& h, unsigned short& l) {
    __nv_bfloat16 hb = __float2bfloat16_rn(v);
    h = __bfloat16_as_ushort(hb);
    l = __bfloat16_as_ushort(__float2bfloat16_rn(v - __bfloat162float(hb)));
}

// ---------------------------------------------------------------------------
// Weight prep
// ---------------------------------------------------------------------------
__global__ void k_split_w1(const float* __restrict__ w,
                           const float* __restrict__ gma,
                           const float* __restrict__ var) {
    int idx = blockIdx.x * 256 + threadIdx.x;
    if (idx >= COUT1 * K1) return;
    int n = idx / K1;
    float scale = gma[n] * rsqrtf(var[n] + 1e-5f);
    float v = w[idx] * scale;
    unsigned short h, l;
    split_bf16(v, h, l);
    g_w1hi[idx] = __ushort_as_bfloat16(h);
    g_w1lo[idx] = __ushort_as_bfloat16(l);
}

__global__ void k_split_w2(const float* __restrict__ w) {
    __shared__ float tile[32][33];
    int kb = blockIdx.x * 32, nb = blockIdx.y * 32;
    int txd = threadIdx.x, tyd = threadIdx.y;
#pragma unroll
    for (int r = 0; r < 4; r++) {
        int n = nb + tyd + r * 8;
        tile[tyd + r * 8][txd] = (n < COUT2) ? w[(size_t)n * K2 + kb + txd] : 0.0f;
    }
    __syncthreads();
    int n = nb + txd;
#pragma unroll
    for (int r = 0; r < 4; r++) {
        int k = kb + tyd + r * 8;
        unsigned short h, l;
        split_bf16(tile[txd][tyd + r * 8], h, l);
        g_w2hi[(size_t)k * N2PAD + n] = __ushort_as_bfloat16(h);
        g_w2lo[(size_t)k * N2PAD + n] = __ushort_as_bfloat16(l);
    }
}

// ---------------------------------------------------------------------------
// Conv1: wmma bf16x3 implicit GEMM. CTA 128x128, 512 thr, warp tile 32x32.
// ---------------------------------------------------------------------------
__global__ __launch_bounds__(512)
void k_conv1_wm(const float* __restrict__ feat,
                const float* __restrict__ gma, const float* __restrict__ bet,
                const float* __restrict__ mea, const float* __restrict__ var) {
    extern __shared__ __align__(16) char smraw[];
    __nv_bfloat16* smb = (__nv_bfloat16*)smraw;
    float* smf = (float*)smraw;

    const int tid = threadIdx.x;
    const int w = tid >> 5;
    const int wm = w & 3, wn = w >> 2;     // 4x4 warp grid
    const int m0 = blockIdx.x * 128;
    const int n0 = blockIdx.y * 128;

    // A gather: 4 threads per m-row, 8 k each
    const int arow = tid >> 2;
    const int ks = (tid & 3) * 8;
    const int m = m0 + arow;
    const int bimg = m >> 10;
    const int pos = m & 1023;
    const int ay = pos >> 5, ax = pos & 31;
    const float* fbase = feat + ((size_t)bimg * CIN << 10);

    // B loader: 4 threads per n-row, 8 k each (one 16B chunk hi + one lo)
    const int brow = tid >> 2;
    const int bks = (tid & 3) * 8;

    wmma::fragment<wmma::accumulator, 16, 16, 16, float> acc[2][2];
#pragma unroll
    for (int i = 0; i < 2; i++)
#pragma unroll
        for (int j = 0; j < 2; j++) wmma::fill_fragment(acc[i][j], 0.0f);

    float fa[8];
    uint4 bh, bl;

    auto gatherA = [&](int kc) {
#pragma unroll
        for (int j = 0; j < 8; j++) {
            int k = kc + ks + j;
            int c = k / 9;
            int q = k - 9 * c;
            int r = q / 3;
            int s = q - 3 * r;
            int iy = ay + r - 1, ix = ax + s - 1;
            float v = 0.f;
            if ((unsigned)iy < 32u && (unsigned)ix < 32u)
                v = fbase[(c << 10) + (iy << 5) + ix];
            fa[j] = v;
        }
    };
    auto loadB = [&](int kc) {
        bh = *(const uint4*)(g_w1hi + (size_t)(n0 + brow) * K1 + kc + bks);
        bl = *(const uint4*)(g_w1lo + (size_t)(n0 + brow) * K1 + kc + bks);
    };
    auto storeStage = [&](int st) {
        uint4 hv, lv;
        unsigned short* hp = (unsigned short*)&hv;
        unsigned short* lp = (unsigned short*)&lv;
#pragma unroll
        for (int j = 0; j < 8; j++) split_bf16(fa[j], hp[j], lp[j]);
        __nv_bfloat16* base = smb + st * C1_STAGE;
        int ao = arow * SA1 + ks;
        *(uint4*)(base + C1_AHI + ao) = hv;
        *(uint4*)(base + C1_ALO + ao) = lv;
        int bo = brow * SA1 + bks;
        *(uint4*)(base + C1_BHI + bo) = bh;
        *(uint4*)(base + C1_BLO + bo) = bl;
    };

    gatherA(0); loadB(0); storeStage(0);
    __syncthreads();

    for (int kt = 0; kt < NKT1; kt++) {
        const int cur = kt & 1;
        if (kt + 1 < NKT1) { gatherA((kt + 1) * KC); loadB((kt + 1) * KC); }

        const __nv_bfloat16* base = smb + cur * C1_STAGE;
#pragma unroll
        for (int kk = 0; kk < KC; kk += 16) {
            wmma::fragment<wmma::matrix_a, 16, 16, 16, __nv_bfloat16, wmma::row_major> af[2];
            wmma::fragment<wmma::matrix_b, 16, 16, 16, __nv_bfloat16, wmma::col_major> bhf[2], blf[2];
            // Ahi, Bhi
#pragma unroll
            for (int i = 0; i < 2; i++)
                wmma::load_matrix_sync(af[i], base + C1_AHI + (wm * 32 + i * 16) * SA1 + kk, SA1);
#pragma unroll
            for (int j = 0; j < 2; j++)
                wmma::load_matrix_sync(bhf[j], base + C1_BHI + (wn * 32 + j * 16) * SA1 + kk, SA1);
#pragma unroll
            for (int i = 0; i < 2; i++)
#pragma unroll
                for (int j = 0; j < 2; j++)
                    wmma::mma_sync(acc[i][j], af[i], bhf[j], acc[i][j]);
            // Ahi * Blo
#pragma unroll
            for (int j = 0; j < 2; j++)
                wmma::load_matrix_sync(blf[j], base + C1_BLO + (wn * 32 + j * 16) * SA1 + kk, SA1);
#pragma unroll
            for (int i = 0; i < 2; i++)
#pragma unroll
                for (int j = 0; j < 2; j++)
                    wmma::mma_sync(acc[i][j], af[i], blf[j], acc[i][j]);
            // Alo * Bhi (reuse af registers)
#pragma unroll
            for (int i = 0; i < 2; i++)
                wmma::load_matrix_sync(af[i], base + C1_ALO + (wm * 32 + i * 16) * SA1 + kk, SA1);
#pragma unroll
            for (int i = 0; i < 2; i++)
#pragma unroll
                for (int j = 0; j < 2; j++)
                    wmma::mma_sync(acc[i][j], af[i], bhf[j], acc[i][j]);
        }
        if (kt + 1 < NKT1) storeStage(cur ^ 1);
        __syncthreads();
    }

    // Epilogue: acc -> smem col-major (element (m,n) at smf[n*128+m])
#pragma unroll
    for (int i = 0; i < 2; i++)
#pragma unroll
        for (int j = 0; j < 2; j++)
            wmma::store_matrix_sync(smf + (wn * 32 + j * 16) * 128 + wm * 32 + i * 16,
                                    acc[i][j], 128, wmma::mem_col_major);
    __syncthreads();

    // BN + leaky, split to bf16 hi/lo, store [k][m]
#pragma unroll
    for (int it = 0; it < 8; it++) {
        int id = it * 512 + tid;
        int ncol = id >> 5;
        int r4 = (id & 31) * 4;
        float4 v = *(const float4*)(smf + ncol * 128 + r4);
        int n = n0 + ncol;
        float scale = gma[n] * rsqrtf(var[n] + 1e-5f);
        float bias = bet[n] - mea[n] * scale;
        float t;
        unsigned short h[4], l[4];
        t = v.x + bias; t = t > 0.f ? t : 0.1f * t; split_bf16(t, h[0], l[0]);
        t = v.y + bias; t = t > 0.f ? t : 0.1f * t; split_bf16(t, h[1], l[1]);
        t = v.z + bias; t = t > 0.f ? t : 0.1f * t; split_bf16(t, h[2], l[2]);
        t = v.w + bias; t = t > 0.f ? t : 0.1f * t; split_bf16(t, h[3], l[3]);
        size_t go = (size_t)n * MTOT + m0 + r4;
        *(uint2*)(g_xhi + go) = *(const uint2*)h;
        *(uint2*)(g_xlo + go) = *(const uint2*)l;
    }
}

// ---------------------------------------------------------------------------
// Conv2: wmma bf16x3 GEMM. CTA 128x128, 512 thr, warp tile 32x32.
// ---------------------------------------------------------------------------
__global__ __launch_bounds__(512)
void k_conv2_wm(const float* __restrict__ bias2) {
    extern __shared__ __align__(16) char smraw[];
    __nv_bfloat16* smb = (__nv_bfloat16*)smraw;
    float* smf = (float*)smraw;

    const int tid = threadIdx.x;
    const int w = tid >> 5;
    const int wm = w & 3, wn = w >> 2;
    const int m0 = blockIdx.x * 128;
    const int n0 = blockIdx.y * 128;

    const int krow = tid >> 4;          // 0..31
    const int seg = (tid & 15) * 8;     // 0..120, 16B chunks

    wmma::fragment<wmma::accumulator, 16, 16, 16, float> acc[2][2];
#pragma unroll
    for (int i = 0; i < 2; i++)
#pragma unroll
        for (int j = 0; j < 2; j++) wmma::fill_fragment(acc[i][j], 0.0f);

    uint4 ah, al, bh, bl;

    auto loadG = [&](int kc) {
        ah = *(const uint4*)(g_xhi + (size_t)(kc + krow) * MTOT + m0 + seg);
        al = *(const uint4*)(g_xlo + (size_t)(kc + krow) * MTOT + m0 + seg);
        bh = *(const uint4*)(g_w2hi + (size_t)(kc + krow) * N2PAD + n0 + seg);
        bl = *(const uint4*)(g_w2lo + (size_t)(kc + krow) * N2PAD + n0 + seg);
    };
    auto storeStage = [&](int st) {
        __nv_bfloat16* base = smb + st * C2_STAGE;
        int o = krow * SA2 + seg;
        *(uint4*)(base + C2_AHI + o) = ah;
        *(uint4*)(base + C2_ALO + o) = al;
        *(uint4*)(base + C2_BHI + o) = bh;
        *(uint4*)(base + C2_BLO + o) = bl;
    };

    loadG(0); storeStage(0);
    __syncthreads();

    for (int kt = 0; kt < NKT2; kt++) {
        const int cur = kt & 1;
        if (kt + 1 < NKT2) loadG((kt + 1) * KC);

        const __nv_bfloat16* base = smb + cur * C2_STAGE;
#pragma unroll
        for (int kk = 0; kk < KC; kk += 16) {
            wmma::fragment<wmma::matrix_a, 16, 16, 16, __nv_bfloat16, wmma::col_major> af[2];
            wmma::fragment<wmma::matrix_b, 16, 16, 16, __nv_bfloat16, wmma::row_major> bhf[2], blf[2];
#pragma unroll
            for (int i = 0; i < 2; i++)
                wmma::load_matrix_sync(af[i], base + C2_AHI + kk * SA2 + wm * 32 + i * 16, SA2);
#pragma unroll
            for (int j = 0; j < 2; j++)
                wmma::load_matrix_sync(bhf[j], base + C2_BHI + kk * SA2 + wn * 32 + j * 16, SA2);
#pragma unroll
            for (int i = 0; i < 2; i++)
#pragma unroll
                for (int j = 0; j < 2; j++)
                    wmma::mma_sync(acc[i][j], af[i], bhf[j], acc[i][j]);
#pragma unroll
            for (int j = 0; j < 2; j++)
                wmma::load_matrix_sync(blf[j], base + C2_BLO + kk * SA2 + wn * 32 + j * 16, SA2);
#pragma unroll
            for (int i = 0; i < 2; i++)
#pragma unroll
                for (int j = 0; j < 2; j++)
                    wmma::mma_sync(acc[i][j], af[i], blf[j], acc[i][j]);
#pragma unroll
            for (int i = 0; i < 2; i++)
                wmma::load_matrix_sync(af[i], base + C2_ALO + kk * SA2 + wm * 32 + i * 16, SA2);
#pragma unroll
            for (int i = 0; i < 2; i++)
#pragma unroll
                for (int j = 0; j < 2; j++)
                    wmma::mma_sync(acc[i][j], af[i], bhf[j], acc[i][j]);
        }
        if (kt + 1 < NKT2) storeStage(cur ^ 1);
        __syncthreads();
    }

    // Epilogue: acc -> smem row-major, + bias -> g_p
#pragma unroll
    for (int i = 0; i < 2; i++)
#pragma unroll
        for (int j = 0; j < 2; j++)
            wmma::store_matrix_sync(smf + (wm * 32 + i * 16) * 128 + wn * 32 + j * 16,
                                    acc[i][j], 128, wmma::mem_row_major);
    __syncthreads();

#pragma unroll
    for (int it = 0; it < 8; it++) {
        int id = it * 512 + tid;
        int mrow = id >> 5;
        int nc4 = (id & 31) * 4;
        float4 v = *(const float4*)(smf + mrow * 128 + nc4);
        int n = n0 + nc4;
        float* dst = g_p + (size_t)(m0 + mrow) * COUT2 + n;
        if (n + 0 < COUT2) dst[0] = v.x + bias2[n + 0];
        if (n + 1 < COUT2) dst[1] = v.y + bias2[n + 1];
        if (n + 2 < COUT2) dst[2] = v.z + bias2[n + 2];
        if (n + 3 < COUT2) dst[3] = v.w + bias2[n + 3];
    }
}

// ---------------------------------------------------------------------------
// Decode: one warp per (position, anchor)
// ---------------------------------------------------------------------------
__global__ void k_decode(float* __restrict__ out) {
    int g = blockIdx.x * (blockDim.x >> 5) + (threadIdx.x >> 5);
    int lane = threadIdx.x & 31;
    if (g >= MTOT * 5) return;
    int m = g / 5;
    int a = g - m * 5;
    const float* base = g_p + (size_t)m * COUT2 + a * 85;

    float t0 = base[0], t1 = base[1], t2 = base[2], t3 = base[3], t4 = base[4];

    float l0 = base[5 + lane];
    float l1 = base[5 + 32 + lane];
    float best = l0; int bi = lane;
    if (l1 > best) { best = l1; bi = lane + 32; }
    float l2 = -3.4e38f;
    if (lane < 16) {
        l2 = base[5 + 64 + lane];
        if (l2 > best) { best = l2; bi = lane + 64; }
    }
#pragma unroll
    for (int off = 16; off; off >>= 1) {
        float ob = __shfl_down_sync(0xffffffffu, best, off);
        int   oi = __shfl_down_sync(0xffffffffu, bi, off);
        if (ob > best || (ob == best && oi < bi)) { best = ob; bi = oi; }
    }
    float mx = __shfl_sync(0xffffffffu, best, 0);
    int gidx = __shfl_sync(0xffffffffu, bi, 0);

    float s = expf(l0 - mx) + expf(l1 - mx) + ((lane < 16) ? expf(l2 - mx) : 0.f);
#pragma unroll
    for (int off = 16; off; off >>= 1)
        s += __shfl_down_sync(0xffffffffu, s, off);

    if (lane == 0) {
        float bx = 1.f / (1.f + expf(-t0));
        float by = 1.f / (1.f + expf(-t1));
        float bw = expf(fminf(t2, 8.f));
        float bh = expf(fminf(t3, 8.f));
        float obj = 1.f / (1.f + expf(-t4));
        float score = obj / s;

        int b = m >> 10;
        int pos = m & 1023;
        int gy = pos >> 5, gx = pos & 31;
        float cx = (bx + (float)gx) * 32.f;
        float cy = (by + (float)gy) * 32.f;
        float pw = c_anc_w[a] * bw;
        float ph = c_anc_h[a] * bh;
        float x1 = fminf(fmaxf(cx - 0.5f * pw, 0.f), 1023.f);
        float y1 = fminf(fmaxf(cy - 0.5f * ph, 0.f), 1023.f);
        float x2 = fminf(fmaxf(cx + 0.5f * pw, 0.f), 1023.f);
        float y2 = fminf(fmaxf(cy + 0.5f * ph, 0.f), 1023.f);

        int idxo = pos * 5 + a;
        float* o5 = out + ((size_t)b * 5120 + idxo) * 5;
        o5[0] = x1; o5[1] = y1; o5[2] = x2; o5[3] = y2; o5[4] = score;
        out[(size_t)NBATCH * 5120 * 5 + (size_t)b * 5120 + idxo] = (float)gidx;
    }
}

// ---------------------------------------------------------------------------
extern "C" void kernel_launch(void* const* d_in, const int* in_sizes, int n_in,
                              void* d_out, int out_size) {
    const float* feat = (const float*)d_in[0];
    const float* w1   = (const float*)d_in[1];
    const float* gma  = (const float*)d_in[2];
    const float* bet  = (const float*)d_in[3];
    const float* mea  = (const float*)d_in[4];
    const float* var  = (const float*)d_in[5];
    const float* w2   = (const float*)d_in[6];
    const float* b2   = (const float*)d_in[7];
    float* out = (float*)d_out;

    static int attr_set = 0;
    if (!attr_set) {
        cudaFuncSetAttribute(k_conv1_wm, cudaFuncAttributeMaxDynamicSharedMemorySize, C1_SMEM_B);
        cudaFuncSetAttribute(k_conv2_wm, cudaFuncAttributeMaxDynamicSharedMemorySize, C2_SMEM_B);
        attr_set = 1;
    }

    k_split_w1<<<(COUT1 * K1 + 255) / 256, 256>>>(w1, gma, var);
    k_split_w2<<<dim3(K2 / 32, N2PAD / 32), dim3(32, 8)>>>(w2);
    k_conv1_wm<<<dim3(MTOT / 128, COUT1 / 128), 512, C1_SMEM_B>>>(feat, gma, bet, mea, var);
    k_conv2_wm<<<dim3(MTOT / 128, N2PAD / 128), 512, C2_SMEM_B>>>(b2);
    k_decode<<<(MTOT * 5 * 32 + 255) / 256, 256>>>(out);
}

// round 7
// speedup vs baseline: 1.7846x; 1.0290x over previous
#include <cuda_runtime.h>
#include <cuda_bf16.h>
#include <mma.h>
#include <math.h>
#include <stdint.h>

using namespace nvcuda;

// Problem constants
#define CIN    512
#define COUT1  1024
#define NBATCH 32
#define K1     4608          // CIN*9
#define MTOT   32768         // NBATCH*32*32
#define COUT2  425
#define N2PAD  512
#define K2     1024

#define KC     32
#define NKT1   (K1 / KC)     // 144
#define NKT2   (K2 / KC)     // 32

// conv1 smem (elements of bf16): CTA 256x128, pitch 40
#define C1_SA      40
#define C1_AHI     0
#define C1_ALO     10240
#define C1_BHI     20480
#define C1_BLO     25600
#define C1_STAGE   30720
#define C1_SMEM_B  (3 * C1_STAGE * 2)     // 184320 bytes

// conv2 smem: A [k][m] pitch 264, B [k][n] pitch 136
#define C2_SAM     264
#define C2_SBN     136
#define C2_AHI     0
#define C2_ALO     8448
#define C2_BHI     16896
#define C2_BLO     21248
#define C2_STAGE   25600
#define C2_SMEM_B  (3 * C2_STAGE * 2)     // 153600 bytes (>= 131072 epilogue floats)

// Scratch (static device memory)
__device__ __align__(16) __nv_bfloat16 g_w1hi[(size_t)COUT1 * K1]; // [n][k]
__device__ __align__(16) __nv_bfloat16 g_w1lo[(size_t)COUT1 * K1];
__device__ __align__(16) __nv_bfloat16 g_xhi[(size_t)COUT1 * MTOT]; // [k][m]
__device__ __align__(16) __nv_bfloat16 g_xlo[(size_t)COUT1 * MTOT];
__device__ __align__(16) __nv_bfloat16 g_w2hi[(size_t)K2 * N2PAD];  // [k][n]
__device__ __align__(16) __nv_bfloat16 g_w2lo[(size_t)K2 * N2PAD];
__device__ float g_p[(size_t)MTOT * COUT2];                         // [m][n]

__constant__ float c_anc_w[5] = {42.f, 98.f, 180.f, 300.f, 400.f};
__constant__ float c_anc_h[5] = {45.f, 130.f, 260.f, 180.f, 400.f};

__device__ __forceinline__ void split_bf16(float v, unsigned short& h, unsigned short& l) {
    __nv_bfloat16 hb = __float2bfloat16_rn(v);
    h = __bfloat16_as_ushort(hb);
    l = __bfloat16_as_ushort(__float2bfloat16_rn(v - __bfloat162float(hb)));
}

__device__ __forceinline__ void cp16(const __nv_bfloat16* smem_dst, const void* gsrc) {
    uint32_t s = (uint32_t)__cvta_generic_to_shared(smem_dst);
    asm volatile("cp.async.cg.shared.global [%0], [%1], 16;" :: "r"(s), "l"(gsrc));
}
__device__ __forceinline__ void cp_commit() {
    asm volatile("cp.async.commit_group;" ::: "memory");
}
template <int N>
__device__ __forceinline__ void cp_wait() {
    asm volatile("cp.async.wait_group %0;" :: "n"(N) : "memory");
}

// ---------------------------------------------------------------------------
// Weight prep
// ---------------------------------------------------------------------------
__global__ void k_split_w1(const float* __restrict__ w,
                           const float* __restrict__ gma,
                           const float* __restrict__ var) {
    int idx = blockIdx.x * 256 + threadIdx.x;
    if (idx >= COUT1 * K1) return;
    int n = idx / K1;
    float scale = gma[n] * rsqrtf(var[n] + 1e-5f);
    float v = w[idx] * scale;
    unsigned short h, l;
    split_bf16(v, h, l);
    g_w1hi[idx] = __ushort_as_bfloat16(h);
    g_w1lo[idx] = __ushort_as_bfloat16(l);
}

__global__ void k_split_w2(const float* __restrict__ w) {
    __shared__ float tile[32][33];
    int kb = blockIdx.x * 32, nb = blockIdx.y * 32;
    int txd = threadIdx.x, tyd = threadIdx.y;
#pragma unroll
    for (int r = 0; r < 4; r++) {
        int n = nb + tyd + r * 8;
        tile[tyd + r * 8][txd] = (n < COUT2) ? w[(size_t)n * K2 + kb + txd] : 0.0f;
    }
    __syncthreads();
    int n = nb + txd;
#pragma unroll
    for (int r = 0; r < 4; r++) {
        int k = kb + tyd + r * 8;
        unsigned short h, l;
        split_bf16(tile[txd][tyd + r * 8], h, l);
        g_w2hi[(size_t)k * N2PAD + n] = __ushort_as_bfloat16(h);
        g_w2lo[(size_t)k * N2PAD + n] = __ushort_as_bfloat16(l);
    }
}

// ---------------------------------------------------------------------------
// Conv1: wmma bf16x3 implicit GEMM. CTA 256x128, 512 thr, warp 64x32, 3-stage.
// ---------------------------------------------------------------------------
__global__ __launch_bounds__(512)
void k_conv1_wm(const float* __restrict__ feat,
                const float* __restrict__ gma, const float* __restrict__ bet,
                const float* __restrict__ mea, const float* __restrict__ var) {
    extern __shared__ __align__(16) char smraw[];
    __nv_bfloat16* smb = (__nv_bfloat16*)smraw;
    float* smf = (float*)smraw;

    const int tid = threadIdx.x;
    const int w = tid >> 5;
    const int wm = w & 3, wn = w >> 2;     // wm: 4 x 64-m, wn: 4 x 32-n
    const int m0 = blockIdx.x * 256;
    const int n0 = blockIdx.y * 128;

    // A gather: 2 threads per m-row, 16 k each
    const int arow = tid >> 1;
    const int ks = (tid & 1) * 16;
    const int m = m0 + arow;
    const int bimg = m >> 10;
    const int pos = m & 1023;
    const int ay = pos >> 5, ax = pos & 31;
    const float* fbase = feat + ((size_t)bimg * CIN << 10);

    // B cp.async: 4 threads per n-row, 8 k each
    const int brow = tid >> 2;
    const int bq = (tid & 3) * 8;

    wmma::fragment<wmma::accumulator, 16, 16, 16, float> acc[4][2];
#pragma unroll
    for (int i = 0; i < 4; i++)
#pragma unroll
        for (int j = 0; j < 2; j++) wmma::fill_fragment(acc[i][j], 0.0f);

    auto loadStage = [&](int st, int kc) {
        __nv_bfloat16* base = smb + st * C1_STAGE;
        // A: gather 16 k in two chunks of 8, split, STS
#pragma unroll
        for (int h = 0; h < 2; h++) {
            int k0 = ks + h * 8;
            uint4 hv, lv;
            unsigned short* hp = (unsigned short*)&hv;
            unsigned short* lp = (unsigned short*)&lv;
#pragma unroll
            for (int j = 0; j < 8; j++) {
                int k = kc + k0 + j;
                int c = k / 9;
                int q = k - 9 * c;
                int r = q / 3;
                int s = q - 3 * r;
                int iy = ay + r - 1, ix = ax + s - 1;
                float v = 0.f;
                if ((unsigned)iy < 32u && (unsigned)ix < 32u)
                    v = fbase[(c << 10) + (iy << 5) + ix];
                split_bf16(v, hp[j], lp[j]);
            }
            *(uint4*)(base + C1_AHI + arow * C1_SA + k0) = hv;
            *(uint4*)(base + C1_ALO + arow * C1_SA + k0) = lv;
        }
        // B: cp.async 16B hi + lo
        size_t go = (size_t)(n0 + brow) * K1 + kc + bq;
        cp16(base + C1_BHI + brow * C1_SA + bq, g_w1hi + go);
        cp16(base + C1_BLO + brow * C1_SA + bq, g_w1lo + go);
    };

    auto compute = [&](int st) {
        const __nv_bfloat16* base = smb + st * C1_STAGE;
#pragma unroll
        for (int kk = 0; kk < KC; kk += 16) {
            wmma::fragment<wmma::matrix_a, 16, 16, 16, __nv_bfloat16, wmma::row_major> af[4];
            wmma::fragment<wmma::matrix_b, 16, 16, 16, __nv_bfloat16, wmma::col_major> bhf[2], blf[2];
#pragma unroll
            for (int i = 0; i < 4; i++)
                wmma::load_matrix_sync(af[i], base + C1_AHI + (wm * 64 + i * 16) * C1_SA + kk, C1_SA);
#pragma unroll
            for (int j = 0; j < 2; j++)
                wmma::load_matrix_sync(bhf[j], base + C1_BHI + (wn * 32 + j * 16) * C1_SA + kk, C1_SA);
#pragma unroll
            for (int i = 0; i < 4; i++)
#pragma unroll
                for (int j = 0; j < 2; j++)
                    wmma::mma_sync(acc[i][j], af[i], bhf[j], acc[i][j]);
#pragma unroll
            for (int j = 0; j < 2; j++)
                wmma::load_matrix_sync(blf[j], base + C1_BLO + (wn * 32 + j * 16) * C1_SA + kk, C1_SA);
#pragma unroll
            for (int i = 0; i < 4; i++)
#pragma unroll
                for (int j = 0; j < 2; j++)
                    wmma::mma_sync(acc[i][j], af[i], blf[j], acc[i][j]);
#pragma unroll
            for (int i = 0; i < 4; i++)
                wmma::load_matrix_sync(af[i], base + C1_ALO + (wm * 64 + i * 16) * C1_SA + kk, C1_SA);
#pragma unroll
            for (int i = 0; i < 4; i++)
#pragma unroll
                for (int j = 0; j < 2; j++)
                    wmma::mma_sync(acc[i][j], af[i], bhf[j], acc[i][j]);
        }
    };

    loadStage(0, 0);
    cp_commit();
    loadStage(1, KC);
    cp_commit();
    cp_wait<1>();
    __syncthreads();

    for (int kt = 0; kt < NKT1; kt++) {
        compute(kt % 3);
        int nk = kt + 2;
        if (nk < NKT1) {
            loadStage(nk % 3, nk * KC);
            cp_commit();
            cp_wait<1>();
        } else {
            cp_wait<0>();
        }
        __syncthreads();
    }

    // Epilogue: acc -> smem col-major (element (m,n) at smf[n*256+m])
    __syncthreads();
#pragma unroll
    for (int i = 0; i < 4; i++)
#pragma unroll
        for (int j = 0; j < 2; j++)
            wmma::store_matrix_sync(smf + (wn * 32 + j * 16) * 256 + wm * 64 + i * 16,
                                    acc[i][j], 256, wmma::mem_col_major);
    __syncthreads();

    // BN + leaky, split to bf16 hi/lo, store [k][m]
#pragma unroll
    for (int it = 0; it < 16; it++) {
        int id = it * 512 + tid;
        int ncol = id >> 6;           // 0..127
        int r4 = (id & 63) * 4;       // 0..252
        float4 v = *(const float4*)(smf + ncol * 256 + r4);
        int n = n0 + ncol;
        float scale = gma[n] * rsqrtf(var[n] + 1e-5f);
        float bias = bet[n] - mea[n] * scale;
        float t;
        unsigned short h[4], l[4];
        t = v.x + bias; t = t > 0.f ? t : 0.1f * t; split_bf16(t, h[0], l[0]);
        t = v.y + bias; t = t > 0.f ? t : 0.1f * t; split_bf16(t, h[1], l[1]);
        t = v.z + bias; t = t > 0.f ? t : 0.1f * t; split_bf16(t, h[2], l[2]);
        t = v.w + bias; t = t > 0.f ? t : 0.1f * t; split_bf16(t, h[3], l[3]);
        size_t go = (size_t)n * MTOT + m0 + r4;
        *(uint2*)(g_xhi + go) = *(const uint2*)h;
        *(uint2*)(g_xlo + go) = *(const uint2*)l;
    }
}

// ---------------------------------------------------------------------------
// Conv2: wmma bf16x3 GEMM. CTA 256x128, 512 thr, warp 64x32, 3-stage cp.async.
// ---------------------------------------------------------------------------
__global__ __launch_bounds__(512)
void k_conv2_wm(const float* __restrict__ bias2) {
    extern __shared__ __align__(16) char smraw[];
    __nv_bfloat16* smb = (__nv_bfloat16*)smraw;
    float* smf = (float*)smraw;

    const int tid = threadIdx.x;
    const int w = tid >> 5;
    const int wm = w & 3, wn = w >> 2;
    const int m0 = blockIdx.x * 256;
    const int n0 = blockIdx.y * 128;

    // A cp.async: 16 threads per k-row, 16 m (two 16B chunks) each
    const int akr = tid >> 4;
    const int aseg = (tid & 15) * 16;
    // B cp.async (tid < 256): 8 threads per k-row, 16 n (two 16B chunks) each
    const int bkr = tid >> 3;
    const int bseg = (tid & 7) * 16;

    wmma::fragment<wmma::accumulator, 16, 16, 16, float> acc[4][2];
#pragma unroll
    for (int i = 0; i < 4; i++)
#pragma unroll
        for (int j = 0; j < 2; j++) wmma::fill_fragment(acc[i][j], 0.0f);

    auto loadStage = [&](int st, int kc) {
        __nv_bfloat16* base = smb + st * C2_STAGE;
        size_t ga = (size_t)(kc + akr) * MTOT + m0 + aseg;
        cp16(base + C2_AHI + akr * C2_SAM + aseg,     g_xhi + ga);
        cp16(base + C2_AHI + akr * C2_SAM + aseg + 8, g_xhi + ga + 8);
        cp16(base + C2_ALO + akr * C2_SAM + aseg,     g_xlo + ga);
        cp16(base + C2_ALO + akr * C2_SAM + aseg + 8, g_xlo + ga + 8);
        if (tid < 256) {
            size_t gb = (size_t)(kc + bkr) * N2PAD + n0 + bseg;
            cp16(base + C2_BHI + bkr * C2_SBN + bseg,     g_w2hi + gb);
            cp16(base + C2_BHI + bkr * C2_SBN + bseg + 8, g_w2hi + gb + 8);
            cp16(base + C2_BLO + bkr * C2_SBN + bseg,     g_w2lo + gb);
            cp16(base + C2_BLO + bkr * C2_SBN + bseg + 8, g_w2lo + gb + 8);
        }
    };

    auto compute = [&](int st) {
        const __nv_bfloat16* base = smb + st * C2_STAGE;
#pragma unroll
        for (int kk = 0; kk < KC; kk += 16) {
            wmma::fragment<wmma::matrix_a, 16, 16, 16, __nv_bfloat16, wmma::col_major> af[4];
            wmma::fragment<wmma::matrix_b, 16, 16, 16, __nv_bfloat16, wmma::row_major> bhf[2], blf[2];
#pragma unroll
            for (int i = 0; i < 4; i++)
                wmma::load_matrix_sync(af[i], base + C2_AHI + kk * C2_SAM + wm * 64 + i * 16, C2_SAM);
#pragma unroll
            for (int j = 0; j < 2; j++)
                wmma::load_matrix_sync(bhf[j], base + C2_BHI + kk * C2_SBN + wn * 32 + j * 16, C2_SBN);
#pragma unroll
            for (int i = 0; i < 4; i++)
#pragma unroll
                for (int j = 0; j < 2; j++)
                    wmma::mma_sync(acc[i][j], af[i], bhf[j], acc[i][j]);
#pragma unroll
            for (int j = 0; j < 2; j++)
                wmma::load_matrix_sync(blf[j], base + C2_BLO + kk * C2_SBN + wn * 32 + j * 16, C2_SBN);
#pragma unroll
            for (int i = 0; i < 4; i++)
#pragma unroll
                for (int j = 0; j < 2; j++)
                    wmma::mma_sync(acc[i][j], af[i], blf[j], acc[i][j]);
#pragma unroll
            for (int i = 0; i < 4; i++)
                wmma::load_matrix_sync(af[i], base + C2_ALO + kk * C2_SAM + wm * 64 + i * 16, C2_SAM);
#pragma unroll
            for (int i = 0; i < 4; i++)
#pragma unroll
                for (int j = 0; j < 2; j++)
                    wmma::mma_sync(acc[i][j], af[i], bhf[j], acc[i][j]);
        }
    };

    loadStage(0, 0);
    cp_commit();
    loadStage(1, KC);
    cp_commit();
    cp_wait<1>();
    __syncthreads();

    for (int kt = 0; kt < NKT2; kt++) {
        compute(kt % 3);
        int nk = kt + 2;
        if (nk < NKT2) {
            loadStage(nk % 3, nk * KC);
            cp_commit();
            cp_wait<1>();
        } else {
            cp_wait<0>();
        }
        __syncthreads();
    }

    // Epilogue: acc -> smem row-major (element (m,n) at smf[m*128+n]), + bias -> g_p
    __syncthreads();
#pragma unroll
    for (int i = 0; i < 4; i++)
#pragma unroll
        for (int j = 0; j < 2; j++)
            wmma::store_matrix_sync(smf + (wm * 64 + i * 16) * 128 + wn * 32 + j * 16,
                                    acc[i][j], 128, wmma::mem_row_major);
    __syncthreads();

#pragma unroll
    for (int it = 0; it < 16; it++) {
        int id = it * 512 + tid;
        int mrow = id >> 5;          // 0..255
        int nc4 = (id & 31) * 4;
        float4 v = *(const float4*)(smf + mrow * 128 + nc4);
        int n = n0 + nc4;
        float* dst = g_p + (size_t)(m0 + mrow) * COUT2 + n;
        if (n + 0 < COUT2) dst[0] = v.x + bias2[n + 0];
        if (n + 1 < COUT2) dst[1] = v.y + bias2[n + 1];
        if (n + 2 < COUT2) dst[2] = v.z + bias2[n + 2];
        if (n + 3 < COUT2) dst[3] = v.w + bias2[n + 3];
    }
}

// ---------------------------------------------------------------------------
// Decode: one warp per (position, anchor)
// ---------------------------------------------------------------------------
__global__ void k_decode(float* __restrict__ out) {
    int g = blockIdx.x * (blockDim.x >> 5) + (threadIdx.x >> 5);
    int lane = threadIdx.x & 31;
    if (g >= MTOT * 5) return;
    int m = g / 5;
    int a = g - m * 5;
    const float* base = g_p + (size_t)m * COUT2 + a * 85;

    float t0 = base[0], t1 = base[1], t2 = base[2], t3 = base[3], t4 = base[4];

    float l0 = base[5 + lane];
    float l1 = base[5 + 32 + lane];
    float best = l0; int bi = lane;
    if (l1 > best) { best = l1; bi = lane + 32; }
    float l2 = -3.4e38f;
    if (lane < 16) {
        l2 = base[5 + 64 + lane];
        if (l2 > best) { best = l2; bi = lane + 64; }
    }
#pragma unroll
    for (int off = 16; off; off >>= 1) {
        float ob = __shfl_down_sync(0xffffffffu, best, off);
        int   oi = __shfl_down_sync(0xffffffffu, bi, off);
        if (ob > best || (ob == best && oi < bi)) { best = ob; bi = oi; }
    }
    float mx = __shfl_sync(0xffffffffu, best, 0);
    int gidx = __shfl_sync(0xffffffffu, bi, 0);

    float s = expf(l0 - mx) + expf(l1 - mx) + ((lane < 16) ? expf(l2 - mx) : 0.f);
#pragma unroll
    for (int off = 16; off; off >>= 1)
        s += __shfl_down_sync(0xffffffffu, s, off);

    if (lane == 0) {
        float bx = 1.f / (1.f + expf(-t0));
        float by = 1.f / (1.f + expf(-t1));
        float bw = expf(fminf(t2, 8.f));
        float bh = expf(fminf(t3, 8.f));
        float obj = 1.f / (1.f + expf(-t4));
        float score = obj / s;

        int b = m >> 10;
        int pos = m & 1023;
        int gy = pos >> 5, gx = pos & 31;
        float cx = (bx + (float)gx) * 32.f;
        float cy = (by + (float)gy) * 32.f;
        float pw = c_anc_w[a] * bw;
        float ph = c_anc_h[a] * bh;
        float x1 = fminf(fmaxf(cx - 0.5f * pw, 0.f), 1023.f);
        float y1 = fminf(fmaxf(cy - 0.5f * ph, 0.f), 1023.f);
        float x2 = fminf(fmaxf(cx + 0.5f * pw, 0.f), 1023.f);
        float y2 = fminf(fmaxf(cy + 0.5f * ph, 0.f), 1023.f);

        int idxo = pos * 5 + a;
        float* o5 = out + ((size_t)b * 5120 + idxo) * 5;
        o5[0] = x1; o5[1] = y1; o5[2] = x2; o5[3] = y2; o5[4] = score;
        out[(size_t)NBATCH * 5120 * 5 + (size_t)b * 5120 + idxo] = (float)gidx;
    }
}

// ---------------------------------------------------------------------------
extern "C" void kernel_launch(void* const* d_in, const int* in_sizes, int n_in,
                              void* d_out, int out_size) {
    const float* feat = (const float*)d_in[0];
    const float* w1   = (const float*)d_in[1];
    const float* gma  = (const float*)d_in[2];
    const float* bet  = (const float*)d_in[3];
    const float* mea  = (const float*)d_in[4];
    const float* var  = (const float*)d_in[5];
    const float* w2   = (const float*)d_in[6];
    const float* b2   = (const float*)d_in[7];
    float* out = (float*)d_out;

    static int attr_set = 0;
    if (!attr_set) {
        cudaFuncSetAttribute(k_conv1_wm, cudaFuncAttributeMaxDynamicSharedMemorySize, C1_SMEM_B);
        cudaFuncSetAttribute(k_conv2_wm, cudaFuncAttributeMaxDynamicSharedMemorySize, C2_SMEM_B);
        attr_set = 1;
    }

    k_split_w1<<<(COUT1 * K1 + 255) / 256, 256>>>(w1, gma, var);
    k_split_w2<<<dim3(K2 / 32, N2PAD / 32), dim3(32, 8)>>>(w2);
    k_conv1_wm<<<dim3(MTOT / 256, COUT1 / 128), 512, C1_SMEM_B>>>(feat, gma, bet, mea, var);
    k_conv2_wm<<<dim3(MTOT / 256, N2PAD / 128), 512, C2_SMEM_B>>>(b2);
    k_decode<<<(MTOT * 5 * 32 + 255) / 256, 256>>>(out);
}

// round 9
// speedup vs baseline: 1.9654x; 1.1014x over previous
#include <cuda_runtime.h>
#include <cuda_bf16.h>
#include <mma.h>
#include <math.h>
#include <stdint.h>

using namespace nvcuda;

// Problem constants
#define CIN    512
#define COUT1  1024
#define NBATCH 32
#define K1     4608          // CIN*9
#define MTOT   32768         // NBATCH*32*32
#define COUT2  425
#define N2PAD  512
#define K2     1024

#define KC     64
#define NKT1   (K1 / KC)     // 72
#define NKT2   (K2 / KC)     // 16

// conv1 smem (bf16 elements): CTA 256x128, k-pitch 72, 2 stages
#define C1_SA      72
#define C1_AHI     0
#define C1_ALO     18432
#define C1_BHI     36864
#define C1_BLO     46080
#define C1_STAGE   55296
#define C1_SMEM_B  (2 * C1_STAGE * 2)     // 221184 bytes

// conv2 smem: A [k][m] pitch 264, B [k][n] pitch 136, 2 stages
#define C2_SAM     264
#define C2_SBN     136
#define C2_AHI     0
#define C2_ALO     16896
#define C2_BHI     33792
#define C2_BLO     42496
#define C2_STAGE   51200
#define C2_SMEM_B  (2 * C2_STAGE * 2)     // 204800 bytes

// Scratch (static device memory)
__device__ __align__(16) __nv_bfloat16 g_w1hi[(size_t)COUT1 * K1]; // [n][k]
__device__ __align__(16) __nv_bfloat16 g_w1lo[(size_t)COUT1 * K1];
__device__ __align__(16) __nv_bfloat16 g_xhi[(size_t)COUT1 * MTOT]; // [k][m]
__device__ __align__(16) __nv_bfloat16 g_xlo[(size_t)COUT1 * MTOT];
__device__ __align__(16) __nv_bfloat16 g_w2hi[(size_t)K2 * N2PAD];  // [k][n]
__device__ __align__(16) __nv_bfloat16 g_w2lo[(size_t)K2 * N2PAD];
__device__ float g_p[(size_t)MTOT * COUT2];                         // [m][n]

__constant__ float c_anc_w[5] = {42.f, 98.f, 180.f, 300.f, 400.f};
__constant__ float c_anc_h[5] = {45.f, 130.f, 260.f, 180.f, 400.f};

__device__ __forceinline__ void split_bf16(float v, unsigned short& h, unsigned short& l) {
    __nv_bfloat16 hb = __float2bfloat16_rn(v);
    h = __bfloat16_as_ushort(hb);
    l = __bfloat16_as_ushort(__float2bfloat16_rn(v - __bfloat162float(hb)));
}

__device__ __forceinline__ void cp16(const __nv_bfloat16* smem_dst, const void* gsrc) {
    uint32_t s = (uint32_t)__cvta_generic_to_shared(smem_dst);
    asm volatile("cp.async.cg.shared.global [%0], [%1], 16;" :: "r"(s), "l"(gsrc));
}
__device__ __forceinline__ void cp_commit() {
    asm volatile("cp.async.commit_group;" ::: "memory");
}
template <int N>
__device__ __forceinline__ void cp_wait() {
    asm volatile("cp.async.wait_group %0;" :: "n"(N) : "memory");
}

// ---------------------------------------------------------------------------
// Weight prep
// ---------------------------------------------------------------------------
__global__ void k_split_w1(const float* __restrict__ w,
                           const float* __restrict__ gma,
                           const float* __restrict__ var) {
    int idx = blockIdx.x * 256 + threadIdx.x;
    if (idx >= COUT1 * K1) return;
    int n = idx / K1;
    float scale = gma[n] * rsqrtf(var[n] + 1e-5f);
    float v = w[idx] * scale;
    unsigned short h, l;
    split_bf16(v, h, l);
    g_w1hi[idx] = __ushort_as_bfloat16(h);
    g_w1lo[idx] = __ushort_as_bfloat16(l);
}

__global__ void k_split_w2(const float* __restrict__ w) {
    __shared__ float tile[32][33];
    int kb = blockIdx.x * 32, nb = blockIdx.y * 32;
    int txd = threadIdx.x, tyd = threadIdx.y;
#pragma unroll
    for (int r = 0; r < 4; r++) {
        int n = nb + tyd + r * 8;
        tile[tyd + r * 8][txd] = (n < COUT2) ? w[(size_t)n * K2 + kb + txd] : 0.0f;
    }
    __syncthreads();
    int n = nb + txd;
#pragma unroll
    for (int r = 0; r < 4; r++) {
        int k = kb + tyd + r * 8;
        unsigned short h, l;
        split_bf16(tile[txd][tyd + r * 8], h, l);
        g_w2hi[(size_t)k * N2PAD + n] = __ushort_as_bfloat16(h);
        g_w2lo[(size_t)k * N2PAD + n] = __ushort_as_bfloat16(l);
    }
}

// ---------------------------------------------------------------------------
// Conv1: wmma bf16x3 implicit GEMM. CTA 256x128, 512 thr, warp 64x32,
// KC=64, 2-stage cp.async pipeline.
// ---------------------------------------------------------------------------
__global__ __launch_bounds__(512)
void k_conv1_wm(const float* __restrict__ feat,
                const float* __restrict__ gma, const float* __restrict__ bet,
                const float* __restrict__ mea, const float* __restrict__ var) {
    extern __shared__ __align__(16) char smraw[];
    __nv_bfloat16* smb = (__nv_bfloat16*)smraw;
    float* smf = (float*)smraw;

    const int tid = threadIdx.x;
    const int w = tid >> 5;
    const int wm = w & 3, wn = w >> 2;     // wm: 4 x 64-m, wn: 4 x 32-n
    const int m0 = blockIdx.x * 256;
    const int n0 = blockIdx.y * 128;

    // A gather: 2 threads per m-row, 32 k each (4 chunks of 8)
    const int arow = tid >> 1;
    const int ks = (tid & 1) * 32;
    const int m = m0 + arow;
    const int bimg = m >> 10;
    const int pos = m & 1023;
    const int ay = pos >> 5, ax = pos & 31;
    const float* fbase = feat + ((size_t)bimg * CIN << 10);

    // B cp.async: 4 threads per n-row, 16 k (two 16B chunks) each
    const int brow = tid >> 2;
    const int bq = (tid & 3) * 16;

    wmma::fragment<wmma::accumulator, 16, 16, 16, float> acc[4][2];
#pragma unroll
    for (int i = 0; i < 4; i++)
#pragma unroll
        for (int j = 0; j < 2; j++) wmma::fill_fragment(acc[i][j], 0.0f);

    auto loadStage = [&](int st, int kc) {
        __nv_bfloat16* base = smb + st * C1_STAGE;
#pragma unroll
        for (int h = 0; h < 4; h++) {
            int k0 = ks + h * 8;
            uint4 hv, lv;
            unsigned short* hp = (unsigned short*)&hv;
            unsigned short* lp = (unsigned short*)&lv;
#pragma unroll
            for (int j = 0; j < 8; j++) {
                int k = kc + k0 + j;
                int c = k / 9;
                int q = k - 9 * c;
                int r = q / 3;
                int s = q - 3 * r;
                int iy = ay + r - 1, ix = ax + s - 1;
                float v = 0.f;
                if ((unsigned)iy < 32u && (unsigned)ix < 32u)
                    v = fbase[(c << 10) + (iy << 5) + ix];
                split_bf16(v, hp[j], lp[j]);
            }
            *(uint4*)(base + C1_AHI + arow * C1_SA + k0) = hv;
            *(uint4*)(base + C1_ALO + arow * C1_SA + k0) = lv;
        }
        size_t go = (size_t)(n0 + brow) * K1 + kc + bq;
        cp16(base + C1_BHI + brow * C1_SA + bq,     g_w1hi + go);
        cp16(base + C1_BHI + brow * C1_SA + bq + 8, g_w1hi + go + 8);
        cp16(base + C1_BLO + brow * C1_SA + bq,     g_w1lo + go);
        cp16(base + C1_BLO + brow * C1_SA + bq + 8, g_w1lo + go + 8);
    };

    auto compute = [&](int st) {
        const __nv_bfloat16* base = smb + st * C1_STAGE;
#pragma unroll
        for (int kk = 0; kk < KC; kk += 16) {
            wmma::fragment<wmma::matrix_a, 16, 16, 16, __nv_bfloat16, wmma::row_major> af[4];
            wmma::fragment<wmma::matrix_b, 16, 16, 16, __nv_bfloat16, wmma::col_major> bhf[2], blf[2];
#pragma unroll
            for (int i = 0; i < 4; i++)
                wmma::load_matrix_sync(af[i], base + C1_AHI + (wm * 64 + i * 16) * C1_SA + kk, C1_SA);
#pragma unroll
            for (int j = 0; j < 2; j++)
                wmma::load_matrix_sync(bhf[j], base + C1_BHI + (wn * 32 + j * 16) * C1_SA + kk, C1_SA);
#pragma unroll
            for (int i = 0; i < 4; i++)
#pragma unroll
                for (int j = 0; j < 2; j++)
                    wmma::mma_sync(acc[i][j], af[i], bhf[j], acc[i][j]);
#pragma unroll
            for (int j = 0; j < 2; j++)
                wmma::load_matrix_sync(blf[j], base + C1_BLO + (wn * 32 + j * 16) * C1_SA + kk, C1_SA);
#pragma unroll
            for (int i = 0; i < 4; i++)
#pragma unroll
                for (int j = 0; j < 2; j++)
                    wmma::mma_sync(acc[i][j], af[i], blf[j], acc[i][j]);
#pragma unroll
            for (int i = 0; i < 4; i++)
                wmma::load_matrix_sync(af[i], base + C1_ALO + (wm * 64 + i * 16) * C1_SA + kk, C1_SA);
#pragma unroll
            for (int i = 0; i < 4; i++)
#pragma unroll
                for (int j = 0; j < 2; j++)
                    wmma::mma_sync(acc[i][j], af[i], bhf[j], acc[i][j]);
        }
    };

    loadStage(0, 0);
    cp_commit();
    for (int kt = 0; kt < NKT1; kt++) {
        cp_wait<0>();
        __syncthreads();
        if (kt + 1 < NKT1) {
            loadStage((kt + 1) & 1, (kt + 1) * KC);
            cp_commit();
        }
        compute(kt & 1);
    }

    // Epilogue: acc -> smem col-major (element (m,n) at smf[n*256+m])
    __syncthreads();
#pragma unroll
    for (int i = 0; i < 4; i++)
#pragma unroll
        for (int j = 0; j < 2; j++)
            wmma::store_matrix_sync(smf + (wn * 32 + j * 16) * 256 + wm * 64 + i * 16,
                                    acc[i][j], 256, wmma::mem_col_major);
    __syncthreads();

    // BN + leaky, split to bf16 hi/lo, store [k][m]
#pragma unroll
    for (int it = 0; it < 16; it++) {
        int id = it * 512 + tid;
        int ncol = id >> 6;           // 0..127
        int r4 = (id & 63) * 4;       // 0..252
        float4 v = *(const float4*)(smf + ncol * 256 + r4);
        int n = n0 + ncol;
        float scale = gma[n] * rsqrtf(var[n] + 1e-5f);
        float bias = bet[n] - mea[n] * scale;
        float t;
        unsigned short h[4], l[4];
        t = v.x + bias; t = t > 0.f ? t : 0.1f * t; split_bf16(t, h[0], l[0]);
        t = v.y + bias; t = t > 0.f ? t : 0.1f * t; split_bf16(t, h[1], l[1]);
        t = v.z + bias; t = t > 0.f ? t : 0.1f * t; split_bf16(t, h[2], l[2]);
        t = v.w + bias; t = t > 0.f ? t : 0.1f * t; split_bf16(t, h[3], l[3]);
        size_t go = (size_t)n * MTOT + m0 + r4;
        *(uint2*)(g_xhi + go) = *(const uint2*)h;
        *(uint2*)(g_xlo + go) = *(const uint2*)l;
    }
}

// ---------------------------------------------------------------------------
// Conv2: wmma bf16x3 GEMM. CTA 256x128, 512 thr, warp 64x32, KC=64, 2-stage.
// ---------------------------------------------------------------------------
__global__ __launch_bounds__(512)
void k_conv2_wm(const float* __restrict__ bias2) {
    extern __shared__ __align__(16) char smraw[];
    __nv_bfloat16* smb = (__nv_bfloat16*)smraw;
    float* smf = (float*)smraw;

    const int tid = threadIdx.x;
    const int w = tid >> 5;
    const int wm = w & 3, wn = w >> 2;
    const int m0 = blockIdx.x * 256;
    const int n0 = blockIdx.y * 128;

    // A cp.async: 8 threads per k-row, 32 m (four 16B chunks) each
    const int akr = tid >> 3;            // 0..63
    const int aseg = (tid & 7) * 32;
    // B cp.async (tid < 256): 4 threads per k-row, 32 n (four 16B chunks) each
    const int bkr = tid >> 2;            // 0..63
    const int bseg = (tid & 3) * 32;

    wmma::fragment<wmma::accumulator, 16, 16, 16, float> acc[4][2];
#pragma unroll
    for (int i = 0; i < 4; i++)
#pragma unroll
        for (int j = 0; j < 2; j++) wmma::fill_fragment(acc[i][j], 0.0f);

    auto loadStage = [&](int st, int kc) {
        __nv_bfloat16* base = smb + st * C2_STAGE;
        size_t ga = (size_t)(kc + akr) * MTOT + m0 + aseg;
#pragma unroll
        for (int c = 0; c < 4; c++) {
            cp16(base + C2_AHI + akr * C2_SAM + aseg + c * 8, g_xhi + ga + c * 8);
            cp16(base + C2_ALO + akr * C2_SAM + aseg + c * 8, g_xlo + ga + c * 8);
        }
        if (tid < 256) {
            size_t gb = (size_t)(kc + bkr) * N2PAD + n0 + bseg;
#pragma unroll
            for (int c = 0; c < 4; c++) {
                cp16(base + C2_BHI + bkr * C2_SBN + bseg + c * 8, g_w2hi + gb + c * 8);
                cp16(base + C2_BLO + bkr * C2_SBN + bseg + c * 8, g_w2lo + gb + c * 8);
            }
        }
    };

    auto compute = [&](int st) {
        const __nv_bfloat16* base = smb + st * C2_STAGE;
#pragma unroll
        for (int kk = 0; kk < KC; kk += 16) {
            wmma::fragment<wmma::matrix_a, 16, 16, 16, __nv_bfloat16, wmma::col_major> af[4];
            wmma::fragment<wmma::matrix_b, 16, 16, 16, __nv_bfloat16, wmma::row_major> bhf[2], blf[2];
#pragma unroll
            for (int i = 0; i < 4; i++)
                wmma::load_matrix_sync(af[i], base + C2_AHI + kk * C2_SAM + wm * 64 + i * 16, C2_SAM);
#pragma unroll
            for (int j = 0; j < 2; j++)
                wmma::load_matrix_sync(bhf[j], base + C2_BHI + kk * C2_SBN + wn * 32 + j * 16, C2_SBN);
#pragma unroll
            for (int i = 0; i < 4; i++)
#pragma unroll
                for (int j = 0; j < 2; j++)
                    wmma::mma_sync(acc[i][j], af[i], bhf[j], acc[i][j]);
#pragma unroll
            for (int j = 0; j < 2; j++)
                wmma::load_matrix_sync(blf[j], base + C2_BLO + kk * C2_SBN + wn * 32 + j * 16, C2_SBN);
#pragma unroll
            for (int i = 0; i < 4; i++)
#pragma unroll
                for (int j = 0; j < 2; j++)
                    wmma::mma_sync(acc[i][j], af[i], blf[j], acc[i][j]);
#pragma unroll
            for (int i = 0; i < 4; i++)
                wmma::load_matrix_sync(af[i], base + C2_ALO + kk * C2_SAM + wm * 64 + i * 16, C2_SAM);
#pragma unroll
            for (int i = 0; i < 4; i++)
#pragma unroll
                for (int j = 0; j < 2; j++)
                    wmma::mma_sync(acc[i][j], af[i], bhf[j], acc[i][j]);
        }
    };

    loadStage(0, 0);
    cp_commit();
    for (int kt = 0; kt < NKT2; kt++) {
        cp_wait<0>();
        __syncthreads();
        if (kt + 1 < NKT2) {
            loadStage((kt + 1) & 1, (kt + 1) * KC);
            cp_commit();
        }
        compute(kt & 1);
    }

    // Epilogue: acc -> smem row-major (element (m,n) at smf[m*128+n]), + bias -> g_p
    __syncthreads();
#pragma unroll
    for (int i = 0; i < 4; i++)
#pragma unroll
        for (int j = 0; j < 2; j++)
            wmma::store_matrix_sync(smf + (wm * 64 + i * 16) * 128 + wn * 32 + j * 16,
                                    acc[i][j], 128, wmma::mem_row_major);
    __syncthreads();

#pragma unroll
    for (int it = 0; it < 16; it++) {
        int id = it * 512 + tid;
        int mrow = id >> 5;          // 0..255
        int nc4 = (id & 31) * 4;
        float4 v = *(const float4*)(smf + mrow * 128 + nc4);
        int n = n0 + nc4;
        float* dst = g_p + (size_t)(m0 + mrow) * COUT2 + n;
        if (n + 0 < COUT2) dst[0] = v.x + bias2[n + 0];
        if (n + 1 < COUT2) dst[1] = v.y + bias2[n + 1];
        if (n + 2 < COUT2) dst[2] = v.z + bias2[n + 2];
        if (n + 3 < COUT2) dst[3] = v.w + bias2[n + 3];
    }
}

// ---------------------------------------------------------------------------
// Decode: one warp per (position, anchor)
// ---------------------------------------------------------------------------
__global__ void k_decode(float* __restrict__ out) {
    int g = blockIdx.x * (blockDim.x >> 5) + (threadIdx.x >> 5);
    int lane = threadIdx.x & 31;
    if (g >= MTOT * 5) return;
    int m = g / 5;
    int a = g - m * 5;
    const float* base = g_p + (size_t)m * COUT2 + a * 85;

    float t0 = base[0], t1 = base[1], t2 = base[2], t3 = base[3], t4 = base[4];

    float l0 = base[5 + lane];
    float l1 = base[5 + 32 + lane];
    float best = l0; int bi = lane;
    if (l1 > best) { best = l1; bi = lane + 32; }
    float l2 = -3.4e38f;
    if (lane < 16) {
        l2 = base[5 + 64 + lane];
        if (l2 > best) { best = l2; bi = lane + 64; }
    }
#pragma unroll
    for (int off = 16; off; off >>= 1) {
        float ob = __shfl_down_sync(0xffffffffu, best, off);
        int   oi = __shfl_down_sync(0xffffffffu, bi, off);
        if (ob > best || (ob == best && oi < bi)) { best = ob; bi = oi; }
    }
    float mx = __shfl_sync(0xffffffffu, best, 0);
    int gidx = __shfl_sync(0xffffffffu, bi, 0);

    float s = expf(l0 - mx) + expf(l1 - mx) + ((lane < 16) ? expf(l2 - mx) : 0.f);
#pragma unroll
    for (int off = 16; off; off >>= 1)
        s += __shfl_down_sync(0xffffffffu, s, off);

    if (lane == 0) {
        float bx = 1.f / (1.f + expf(-t0));
        float by = 1.f / (1.f + expf(-t1));
        float bw = expf(fminf(t2, 8.f));
        float bh = expf(fminf(t3, 8.f));
        float obj = 1.f / (1.f + expf(-t4));
        float score = obj / s;

        int b = m >> 10;
        int pos = m & 1023;
        int gy = pos >> 5, gx = pos & 31;
        float cx = (bx + (float)gx) * 32.f;
        float cy = (by + (float)gy) * 32.f;
        float pw = c_anc_w[a] * bw;
        float ph = c_anc_h[a] * bh;
        float x1 = fminf(fmaxf(cx - 0.5f * pw, 0.f), 1023.f);
        float y1 = fminf(fmaxf(cy - 0.5f * ph, 0.f), 1023.f);
        float x2 = fminf(fmaxf(cx + 0.5f * pw, 0.f), 1023.f);
        float y2 = fminf(fmaxf(cy + 0.5f * ph, 0.f), 1023.f);

        int idxo = pos * 5 + a;
        float* o5 = out + ((size_t)b * 5120 + idxo) * 5;
        o5[0] = x1; o5[1] = y1; o5[2] = x2; o5[3] = y2; o5[4] = score;
        out[(size_t)NBATCH * 5120 * 5 + (size_t)b * 5120 + idxo] = (float)gidx;
    }
}

// ---------------------------------------------------------------------------
extern "C" void kernel_launch(void* const* d_in, const int* in_sizes, int n_in,
                              void* d_out, int out_size) {
    const float* feat = (const float*)d_in[0];
    const float* w1   = (const float*)d_in[1];
    const float* gma  = (const float*)d_in[2];
    const float* bet  = (const float*)d_in[3];
    const float* mea  = (const float*)d_in[4];
    const float* var  = (const float*)d_in[5];
    const float* w2   = (const float*)d_in[6];
    const float* b2   = (const float*)d_in[7];
    float* out = (float*)d_out;

    static int attr_set = 0;
    if (!attr_set) {
        cudaFuncSetAttribute(k_conv1_wm, cudaFuncAttributeMaxDynamicSharedMemorySize, C1_SMEM_B);
        cudaFuncSetAttribute(k_conv2_wm, cudaFuncAttributeMaxDynamicSharedMemorySize, C2_SMEM_B);
        attr_set = 1;
    }

    k_split_w1<<<(COUT1 * K1 + 255) / 256, 256>>>(w1, gma, var);
    k_split_w2<<<dim3(K2 / 32, N2PAD / 32), dim3(32, 8)>>>(w2);
    k_conv1_wm<<<dim3(MTOT / 256, COUT1 / 128), 512, C1_SMEM_B>>>(feat, gma, bet, mea, var);
    k_conv2_wm<<<dim3(MTOT / 256, N2PAD / 128), 512, C2_SMEM_B>>>(b2);
    k_decode<<<(MTOT * 5 * 32 + 255) / 256, 256>>>(out);
}

// round 10
// speedup vs baseline: 2.0754x; 1.0559x over previous
#include <cuda_runtime.h>
#include <cuda_bf16.h>
#include <mma.h>
#include <math.h>
#include <stdint.h>

using namespace nvcuda;

// Problem constants
#define CIN    512
#define COUT1  1024
#define NBATCH 32
#define K1     4608          // CIN*9
#define MTOT   32768         // NBATCH*32*32
#define COUT2  425
#define N2PAD  512
#define K2     1024

#define KC     32
#define NKT1   (K1 / KC)     // 144
#define NKT2   (K2 / KC)     // 32

// conv1 smem (bf16 elements): CTA 128x128, k-pitch 40, 2 stages
#define C1_SA      40
#define C1_AHI     0
#define C1_ALO     5120
#define C1_BHI     10240
#define C1_BLO     15360
#define C1_STAGE   20480
#define C1_SMEM_B  (2 * C1_STAGE * 2)     // 81920 bytes  -> 2 CTAs/SM

// conv2 smem: A [k][m] pitch 136, B [k][n] pitch 136, 2 stages
#define C2_SAM     136
#define C2_SBN     136
#define C2_AHI     0
#define C2_ALO     4352
#define C2_BHI     8704
#define C2_BLO     13056
#define C2_STAGE   17408
#define C2_SMEM_B  (2 * C2_STAGE * 2)     // 69632 bytes -> 2 CTAs/SM (epilogue needs 65536 ok)

// Scratch (static device memory)
__device__ __align__(16) __nv_bfloat16 g_w1hi[(size_t)COUT1 * K1]; // [n][k]
__device__ __align__(16) __nv_bfloat16 g_w1lo[(size_t)COUT1 * K1];
__device__ __align__(16) __nv_bfloat16 g_xhi[(size_t)COUT1 * MTOT]; // [k][m]
__device__ __align__(16) __nv_bfloat16 g_xlo[(size_t)COUT1 * MTOT];
__device__ __align__(16) __nv_bfloat16 g_w2hi[(size_t)K2 * N2PAD];  // [k][n]
__device__ __align__(16) __nv_bfloat16 g_w2lo[(size_t)K2 * N2PAD];
__device__ float g_p[(size_t)MTOT * COUT2];                         // [m][n]

__constant__ float c_anc_w[5] = {42.f, 98.f, 180.f, 300.f, 400.f};
__constant__ float c_anc_h[5] = {45.f, 130.f, 260.f, 180.f, 400.f};

__device__ __forceinline__ void split_bf16(float v, unsigned short& h, unsigned short& l) {
    __nv_bfloat16 hb = __float2bfloat16_rn(v);
    h = __bfloat16_as_ushort(hb);
    l = __bfloat16_as_ushort(__float2bfloat16_rn(v - __bfloat162float(hb)));
}

__device__ __forceinline__ void cp16(const __nv_bfloat16* smem_dst, const void* gsrc) {
    uint32_t s = (uint32_t)__cvta_generic_to_shared(smem_dst);
    asm volatile("cp.async.cg.shared.global [%0], [%1], 16;" :: "r"(s), "l"(gsrc));
}
__device__ __forceinline__ void cp_commit() {
    asm volatile("cp.async.commit_group;" ::: "memory");
}
template <int N>
__device__ __forceinline__ void cp_wait() {
    asm volatile("cp.async.wait_group %0;" :: "n"(N) : "memory");
}

// ---------------------------------------------------------------------------
// Weight prep
// ---------------------------------------------------------------------------
__global__ void k_split_w1(const float* __restrict__ w,
                           const float* __restrict__ gma,
                           const float* __restrict__ var) {
    int idx = blockIdx.x * 256 + threadIdx.x;
    if (idx >= COUT1 * K1) return;
    int n = idx / K1;
    float scale = gma[n] * rsqrtf(var[n] + 1e-5f);
    float v = w[idx] * scale;
    unsigned short h, l;
    split_bf16(v, h, l);
    g_w1hi[idx] = __ushort_as_bfloat16(h);
    g_w1lo[idx] = __ushort_as_bfloat16(l);
}

__global__ void k_split_w2(const float* __restrict__ w) {
    __shared__ float tile[32][33];
    int kb = blockIdx.x * 32, nb = blockIdx.y * 32;
    int txd = threadIdx.x, tyd = threadIdx.y;
#pragma unroll
    for (int r = 0; r < 4; r++) {
        int n = nb + tyd + r * 8;
        tile[tyd + r * 8][txd] = (n < COUT2) ? w[(size_t)n * K2 + kb + txd] : 0.0f;
    }
    __syncthreads();
    int n = nb + txd;
#pragma unroll
    for (int r = 0; r < 4; r++) {
        int k = kb + tyd + r * 8;
        unsigned short h, l;
        split_bf16(tile[txd][tyd + r * 8], h, l);
        g_w2hi[(size_t)k * N2PAD + n] = __ushort_as_bfloat16(h);
        g_w2lo[(size_t)k * N2PAD + n] = __ushort_as_bfloat16(l);
    }
}

// ---------------------------------------------------------------------------
// Conv1: wmma bf16x3 implicit GEMM. CTA 128x128, 256 thr (8 warps, 2x4),
// warp tile 64x32, KC=32, 2-stage cp.async, 2 CTAs/SM.
// ---------------------------------------------------------------------------
__global__ __launch_bounds__(256, 2)
void k_conv1_wm(const float* __restrict__ feat,
                const float* __restrict__ gma, const float* __restrict__ bet,
                const float* __restrict__ mea, const float* __restrict__ var) {
    extern __shared__ __align__(16) char smraw[];
    __nv_bfloat16* smb = (__nv_bfloat16*)smraw;
    float* smf = (float*)smraw;

    const int tid = threadIdx.x;
    const int w = tid >> 5;
    const int wm = w & 1, wn = w >> 1;     // wm: 2 x 64-m, wn: 4 x 32-n
    const int m0 = blockIdx.x * 128;
    const int n0 = blockIdx.y * 128;

    // A gather: 2 threads per m-row, 16 k each (2 chunks of 8)
    const int arow = tid >> 1;
    const int ks = (tid & 1) * 16;
    const int m = m0 + arow;
    const int bimg = m >> 10;
    const int pos = m & 1023;
    const int ay = pos >> 5, ax = pos & 31;
    const float* fbase = feat + ((size_t)bimg * CIN << 10);

    // B cp.async: 2 threads per n-row, 16 k (two 16B chunks) each
    const int brow = tid >> 1;
    const int bq = (tid & 1) * 16;

    wmma::fragment<wmma::accumulator, 16, 16, 16, float> acc[4][2];
#pragma unroll
    for (int i = 0; i < 4; i++)
#pragma unroll
        for (int j = 0; j < 2; j++) wmma::fill_fragment(acc[i][j], 0.0f);

    auto loadStage = [&](int st, int kc) {
        __nv_bfloat16* base = smb + st * C1_STAGE;
#pragma unroll
        for (int h = 0; h < 2; h++) {
            int k0 = ks + h * 8;
            uint4 hv, lv;
            unsigned short* hp = (unsigned short*)&hv;
            unsigned short* lp = (unsigned short*)&lv;
#pragma unroll
            for (int j = 0; j < 8; j++) {
                int k = kc + k0 + j;
                int c = k / 9;
                int q = k - 9 * c;
                int r = q / 3;
                int s = q - 3 * r;
                int iy = ay + r - 1, ix = ax + s - 1;
                float v = 0.f;
                if ((unsigned)iy < 32u && (unsigned)ix < 32u)
                    v = fbase[(c << 10) + (iy << 5) + ix];
                split_bf16(v, hp[j], lp[j]);
            }
            *(uint4*)(base + C1_AHI + arow * C1_SA + k0) = hv;
            *(uint4*)(base + C1_ALO + arow * C1_SA + k0) = lv;
        }
        size_t go = (size_t)(n0 + brow) * K1 + kc + bq;
        cp16(base + C1_BHI + brow * C1_SA + bq,     g_w1hi + go);
        cp16(base + C1_BHI + brow * C1_SA + bq + 8, g_w1hi + go + 8);
        cp16(base + C1_BLO + brow * C1_SA + bq,     g_w1lo + go);
        cp16(base + C1_BLO + brow * C1_SA + bq + 8, g_w1lo + go + 8);
    };

    auto compute = [&](int st) {
        const __nv_bfloat16* base = smb + st * C1_STAGE;
#pragma unroll
        for (int kk = 0; kk < KC; kk += 16) {
            wmma::fragment<wmma::matrix_a, 16, 16, 16, __nv_bfloat16, wmma::row_major> af[4];
            wmma::fragment<wmma::matrix_b, 16, 16, 16, __nv_bfloat16, wmma::col_major> bhf[2], blf[2];
#pragma unroll
            for (int i = 0; i < 4; i++)
                wmma::load_matrix_sync(af[i], base + C1_AHI + (wm * 64 + i * 16) * C1_SA + kk, C1_SA);
#pragma unroll
            for (int j = 0; j < 2; j++)
                wmma::load_matrix_sync(bhf[j], base + C1_BHI + (wn * 32 + j * 16) * C1_SA + kk, C1_SA);
#pragma unroll
            for (int i = 0; i < 4; i++)
#pragma unroll
                for (int j = 0; j < 2; j++)
                    wmma::mma_sync(acc[i][j], af[i], bhf[j], acc[i][j]);
#pragma unroll
            for (int j = 0; j < 2; j++)
                wmma::load_matrix_sync(blf[j], base + C1_BLO + (wn * 32 + j * 16) * C1_SA + kk, C1_SA);
#pragma unroll
            for (int i = 0; i < 4; i++)
#pragma unroll
                for (int j = 0; j < 2; j++)
                    wmma::mma_sync(acc[i][j], af[i], blf[j], acc[i][j]);
#pragma unroll
            for (int i = 0; i < 4; i++)
                wmma::load_matrix_sync(af[i], base + C1_ALO + (wm * 64 + i * 16) * C1_SA + kk, C1_SA);
#pragma unroll
            for (int i = 0; i < 4; i++)
#pragma unroll
                for (int j = 0; j < 2; j++)
                    wmma::mma_sync(acc[i][j], af[i], bhf[j], acc[i][j]);
        }
    };

    loadStage(0, 0);
    cp_commit();
    for (int kt = 0; kt < NKT1; kt++) {
        cp_wait<0>();
        __syncthreads();
        if (kt + 1 < NKT1) {
            loadStage((kt + 1) & 1, (kt + 1) * KC);
            cp_commit();
        }
        compute(kt & 1);
    }

    // Epilogue: acc -> smem col-major (element (m,n) at smf[n*128+m])
    __syncthreads();
#pragma unroll
    for (int i = 0; i < 4; i++)
#pragma unroll
        for (int j = 0; j < 2; j++)
            wmma::store_matrix_sync(smf + (wn * 32 + j * 16) * 128 + wm * 64 + i * 16,
                                    acc[i][j], 128, wmma::mem_col_major);
    __syncthreads();

    // BN + leaky, split to bf16 hi/lo, store [k][m]
#pragma unroll
    for (int it = 0; it < 16; it++) {
        int id = it * 256 + tid;
        int ncol = id >> 5;           // 0..127
        int r4 = (id & 31) * 4;       // 0..124
        float4 v = *(const float4*)(smf + ncol * 128 + r4);
        int n = n0 + ncol;
        float scale = gma[n] * rsqrtf(var[n] + 1e-5f);
        float bias = bet[n] - mea[n] * scale;
        float t;
        unsigned short h[4], l[4];
        t = v.x + bias; t = t > 0.f ? t : 0.1f * t; split_bf16(t, h[0], l[0]);
        t = v.y + bias; t = t > 0.f ? t : 0.1f * t; split_bf16(t, h[1], l[1]);
        t = v.z + bias; t = t > 0.f ? t : 0.1f * t; split_bf16(t, h[2], l[2]);
        t = v.w + bias; t = t > 0.f ? t : 0.1f * t; split_bf16(t, h[3], l[3]);
        size_t go = (size_t)n * MTOT + m0 + r4;
        *(uint2*)(g_xhi + go) = *(const uint2*)h;
        *(uint2*)(g_xlo + go) = *(const uint2*)l;
    }
}

// ---------------------------------------------------------------------------
// Conv2: wmma bf16x3 GEMM. CTA 128x128, 256 thr, warp 64x32, KC=32, 2-stage.
// ---------------------------------------------------------------------------
__global__ __launch_bounds__(256, 2)
void k_conv2_wm(const float* __restrict__ bias2) {
    extern __shared__ __align__(16) char smraw[];
    __nv_bfloat16* smb = (__nv_bfloat16*)smraw;
    float* smf = (float*)smraw;

    const int tid = threadIdx.x;
    const int w = tid >> 5;
    const int wm = w & 1, wn = w >> 1;
    const int m0 = blockIdx.x * 128;
    const int n0 = blockIdx.y * 128;

    // A cp.async: 8 threads per k-row, 16 m (two 16B chunks) each
    const int akr = tid >> 3;            // 0..31
    const int aseg = (tid & 7) * 16;
    // B cp.async: same geometry over n
    const int bkr = tid >> 3;
    const int bseg = (tid & 7) * 16;

    wmma::fragment<wmma::accumulator, 16, 16, 16, float> acc[4][2];
#pragma unroll
    for (int i = 0; i < 4; i++)
#pragma unroll
        for (int j = 0; j < 2; j++) wmma::fill_fragment(acc[i][j], 0.0f);

    auto loadStage = [&](int st, int kc) {
        __nv_bfloat16* base = smb + st * C2_STAGE;
        size_t ga = (size_t)(kc + akr) * MTOT + m0 + aseg;
        cp16(base + C2_AHI + akr * C2_SAM + aseg,     g_xhi + ga);
        cp16(base + C2_AHI + akr * C2_SAM + aseg + 8, g_xhi + ga + 8);
        cp16(base + C2_ALO + akr * C2_SAM + aseg,     g_xlo + ga);
        cp16(base + C2_ALO + akr * C2_SAM + aseg + 8, g_xlo + ga + 8);
        size_t gb = (size_t)(kc + bkr) * N2PAD + n0 + bseg;
        cp16(base + C2_BHI + bkr * C2_SBN + bseg,     g_w2hi + gb);
        cp16(base + C2_BHI + bkr * C2_SBN + bseg + 8, g_w2hi + gb + 8);
        cp16(base + C2_BLO + bkr * C2_SBN + bseg,     g_w2lo + gb);
        cp16(base + C2_BLO + bkr * C2_SBN + bseg + 8, g_w2lo + gb + 8);
    };

    auto compute = [&](int st) {
        const __nv_bfloat16* base = smb + st * C2_STAGE;
#pragma unroll
        for (int kk = 0; kk < KC; kk += 16) {
            wmma::fragment<wmma::matrix_a, 16, 16, 16, __nv_bfloat16, wmma::col_major> af[4];
            wmma::fragment<wmma::matrix_b, 16, 16, 16, __nv_bfloat16, wmma::row_major> bhf[2], blf[2];
#pragma unroll
            for (int i = 0; i < 4; i++)
                wmma::load_matrix_sync(af[i], base + C2_AHI + kk * C2_SAM + wm * 64 + i * 16, C2_SAM);
#pragma unroll
            for (int j = 0; j < 2; j++)
                wmma::load_matrix_sync(bhf[j], base + C2_BHI + kk * C2_SBN + wn * 32 + j * 16, C2_SBN);
#pragma unroll
            for (int i = 0; i < 4; i++)
#pragma unroll
                for (int j = 0; j < 2; j++)
                    wmma::mma_sync(acc[i][j], af[i], bhf[j], acc[i][j]);
#pragma unroll
            for (int j = 0; j < 2; j++)
                wmma::load_matrix_sync(blf[j], base + C2_BLO + kk * C2_SBN + wn * 32 + j * 16, C2_SBN);
#pragma unroll
            for (int i = 0; i < 4; i++)
#pragma unroll
                for (int j = 0; j < 2; j++)
                    wmma::mma_sync(acc[i][j], af[i], blf[j], acc[i][j]);
#pragma unroll
            for (int i = 0; i < 4; i++)
                wmma::load_matrix_sync(af[i], base + C2_ALO + kk * C2_SAM + wm * 64 + i * 16, C2_SAM);
#pragma unroll
            for (int i = 0; i < 4; i++)
#pragma unroll
                for (int j = 0; j < 2; j++)
                    wmma::mma_sync(acc[i][j], af[i], bhf[j], acc[i][j]);
        }
    };

    loadStage(0, 0);
    cp_commit();
    for (int kt = 0; kt < NKT2; kt++) {
        cp_wait<0>();
        __syncthreads();
        if (kt + 1 < NKT2) {
            loadStage((kt + 1) & 1, (kt + 1) * KC);
            cp_commit();
        }
        compute(kt & 1);
    }

    // Epilogue: acc -> smem row-major (element (m,n) at smf[m*128+n]), + bias -> g_p
    __syncthreads();
#pragma unroll
    for (int i = 0; i < 4; i++)
#pragma unroll
        for (int j = 0; j < 2; j++)
            wmma::store_matrix_sync(smf + (wm * 64 + i * 16) * 128 + wn * 32 + j * 16,
                                    acc[i][j], 128, wmma::mem_row_major);
    __syncthreads();

#pragma unroll
    for (int it = 0; it < 16; it++) {
        int id = it * 256 + tid;
        int mrow = id >> 5;          // 0..127
        int nc4 = (id & 31) * 4;
        float4 v = *(const float4*)(smf + mrow * 128 + nc4);
        int n = n0 + nc4;
        float* dst = g_p + (size_t)(m0 + mrow) * COUT2 + n;
        if (n + 0 < COUT2) dst[0] = v.x + bias2[n + 0];
        if (n + 1 < COUT2) dst[1] = v.y + bias2[n + 1];
        if (n + 2 < COUT2) dst[2] = v.z + bias2[n + 2];
        if (n + 3 < COUT2) dst[3] = v.w + bias2[n + 3];
    }
}

// ---------------------------------------------------------------------------
// Decode: one warp per (position, anchor)
// ---------------------------------------------------------------------------
__global__ void k_decode(float* __restrict__ out) {
    int g = blockIdx.x * (blockDim.x >> 5) + (threadIdx.x >> 5);
    int lane = threadIdx.x & 31;
    if (g >= MTOT * 5) return;
    int m = g / 5;
    int a = g - m * 5;
    const float* base = g_p + (size_t)m * COUT2 + a * 85;

    float t0 = base[0], t1 = base[1], t2 = base[2], t3 = base[3], t4 = base[4];

    float l0 = base[5 + lane];
    float l1 = base[5 + 32 + lane];
    float best = l0; int bi = lane;
    if (l1 > best) { best = l1; bi = lane + 32; }
    float l2 = -3.4e38f;
    if (lane < 16) {
        l2 = base[5 + 64 + lane];
        if (l2 > best) { best = l2; bi = lane + 64; }
    }
#pragma unroll
    for (int off = 16; off; off >>= 1) {
        float ob = __shfl_down_sync(0xffffffffu, best, off);
        int   oi = __shfl_down_sync(0xffffffffu, bi, off);
        if (ob > best || (ob == best && oi < bi)) { best = ob; bi = oi; }
    }
    float mx = __shfl_sync(0xffffffffu, best, 0);
    int gidx = __shfl_sync(0xffffffffu, bi, 0);

    float s = expf(l0 - mx) + expf(l1 - mx) + ((lane < 16) ? expf(l2 - mx) : 0.f);
#pragma unroll
    for (int off = 16; off; off >>= 1)
        s += __shfl_down_sync(0xffffffffu, s, off);

    if (lane == 0) {
        float bx = 1.f / (1.f + expf(-t0));
        float by = 1.f / (1.f + expf(-t1));
        float bw = expf(fminf(t2, 8.f));
        float bh = expf(fminf(t3, 8.f));
        float obj = 1.f / (1.f + expf(-t4));
        float score = obj / s;

        int b = m >> 10;
        int pos = m & 1023;
        int gy = pos >> 5, gx = pos & 31;
        float cx = (bx + (float)gx) * 32.f;
        float cy = (by + (float)gy) * 32.f;
        float pw = c_anc_w[a] * bw;
        float ph = c_anc_h[a] * bh;
        float x1 = fminf(fmaxf(cx - 0.5f * pw, 0.f), 1023.f);
        float y1 = fminf(fmaxf(cy - 0.5f * ph, 0.f), 1023.f);
        float x2 = fminf(fmaxf(cx + 0.5f * pw, 0.f), 1023.f);
        float y2 = fminf(fmaxf(cy + 0.5f * ph, 0.f), 1023.f);

        int idxo = pos * 5 + a;
        float* o5 = out + ((size_t)b * 5120 + idxo) * 5;
        o5[0] = x1; o5[1] = y1; o5[2] = x2; o5[3] = y2; o5[4] = score;
        out[(size_t)NBATCH * 5120 * 5 + (size_t)b * 5120 + idxo] = (float)gidx;
    }
}

// ---------------------------------------------------------------------------
extern "C" void kernel_launch(void* const* d_in, const int* in_sizes, int n_in,
                              void* d_out, int out_size) {
    const float* feat = (const float*)d_in[0];
    const float* w1   = (const float*)d_in[1];
    const float* gma  = (const float*)d_in[2];
    const float* bet  = (const float*)d_in[3];
    const float* mea  = (const float*)d_in[4];
    const float* var  = (const float*)d_in[5];
    const float* w2   = (const float*)d_in[6];
    const float* b2   = (const float*)d_in[7];
    float* out = (float*)d_out;

    static int attr_set = 0;
    if (!attr_set) {
        cudaFuncSetAttribute(k_conv1_wm, cudaFuncAttributeMaxDynamicSharedMemorySize, C1_SMEM_B);
        cudaFuncSetAttribute(k_conv2_wm, cudaFuncAttributeMaxDynamicSharedMemorySize, C2_SMEM_B);
        attr_set = 1;
    }

    k_split_w1<<<(COUT1 * K1 + 255) / 256, 256>>>(w1, gma, var);
    k_split_w2<<<dim3(K2 / 32, N2PAD / 32), dim3(32, 8)>>>(w2);
    k_conv1_wm<<<dim3(MTOT / 128, COUT1 / 128), 256, C1_SMEM_B>>>(feat, gma, bet, mea, var);
    k_conv2_wm<<<dim3(MTOT / 128, N2PAD / 128), 256, C2_SMEM_B>>>(b2);
    k_decode<<<(MTOT * 5 * 32 + 255) / 256, 256>>>(out);
}

// round 11
// speedup vs baseline: 2.1040x; 1.0138x over previous
#include <cuda_runtime.h>
#include <cuda_bf16.h>
#include <mma.h>
#include <math.h>
#include <stdint.h>

using namespace nvcuda;

// Problem constants
#define CIN    512
#define COUT1  1024
#define NBATCH 32
#define K1     4608          // CIN*9
#define MTOT   32768         // NBATCH*32*32
#define COUT2  425
#define N2PAD  512
#define K2     1024

#define KC     32
#define NKT1   (K1 / KC)     // 144
#define NKT2   (K2 / KC)     // 32

// conv1 smem (bf16 elements): A [k][m] pitch 136 (32 rows), B [n][k] pitch 40 (128 rows)
#define C1_PM      136
#define C1_PK      40
#define C1_AHI     0
#define C1_ALO     4352
#define C1_BHI     8704
#define C1_BLO     13824
#define C1_STAGE   18944
#define C1_SMEM_B  (2 * C1_STAGE * 2)     // 75776 bytes -> 2 CTAs/SM

// conv2 smem: A [k][m] pitch 136, B [k][n] pitch 136, 2 stages
#define C2_SAM     136
#define C2_SBN     136
#define C2_AHI     0
#define C2_ALO     4352
#define C2_BHI     8704
#define C2_BLO     13056
#define C2_STAGE   17408
#define C2_SMEM_B  (2 * C2_STAGE * 2)     // 69632 bytes -> 2 CTAs/SM

// Scratch (static device memory)
__device__ __align__(16) __nv_bfloat16 g_ahi[(size_t)K1 * MTOT];   // im2col A, [k][m]
__device__ __align__(16) __nv_bfloat16 g_alo[(size_t)K1 * MTOT];
__device__ __align__(16) __nv_bfloat16 g_w1hi[(size_t)COUT1 * K1]; // [n][k]
__device__ __align__(16) __nv_bfloat16 g_w1lo[(size_t)COUT1 * K1];
__device__ __align__(16) __nv_bfloat16 g_xhi[(size_t)COUT1 * MTOT]; // [k][m]
__device__ __align__(16) __nv_bfloat16 g_xlo[(size_t)COUT1 * MTOT];
__device__ __align__(16) __nv_bfloat16 g_w2hi[(size_t)K2 * N2PAD];  // [k][n]
__device__ __align__(16) __nv_bfloat16 g_w2lo[(size_t)K2 * N2PAD];
__device__ float g_p[(size_t)MTOT * COUT2];                         // [m][n]

__constant__ float c_anc_w[5] = {42.f, 98.f, 180.f, 300.f, 400.f};
__constant__ float c_anc_h[5] = {45.f, 130.f, 260.f, 180.f, 400.f};

__device__ __forceinline__ void split_bf16(float v, unsigned short& h, unsigned short& l) {
    __nv_bfloat16 hb = __float2bfloat16_rn(v);
    h = __bfloat16_as_ushort(hb);
    l = __bfloat16_as_ushort(__float2bfloat16_rn(v - __bfloat162float(hb)));
}

__device__ __forceinline__ void cp16(const __nv_bfloat16* smem_dst, const void* gsrc) {
    uint32_t s = (uint32_t)__cvta_generic_to_shared(smem_dst);
    asm volatile("cp.async.cg.shared.global [%0], [%1], 16;" :: "r"(s), "l"(gsrc));
}
__device__ __forceinline__ void cp_commit() {
    asm volatile("cp.async.commit_group;" ::: "memory");
}
template <int N>
__device__ __forceinline__ void cp_wait() {
    asm volatile("cp.async.wait_group %0;" :: "n"(N) : "memory");
}

// ---------------------------------------------------------------------------
// Weight prep
// ---------------------------------------------------------------------------
__global__ void k_split_w1(const float* __restrict__ w,
                           const float* __restrict__ gma,
                           const float* __restrict__ var) {
    int idx = blockIdx.x * 256 + threadIdx.x;
    if (idx >= COUT1 * K1) return;
    int n = idx / K1;
    float scale = gma[n] * rsqrtf(var[n] + 1e-5f);
    float v = w[idx] * scale;
    unsigned short h, l;
    split_bf16(v, h, l);
    g_w1hi[idx] = __ushort_as_bfloat16(h);
    g_w1lo[idx] = __ushort_as_bfloat16(l);
}

__global__ void k_split_w2(const float* __restrict__ w) {
    __shared__ float tile[32][33];
    int kb = blockIdx.x * 32, nb = blockIdx.y * 32;
    int txd = threadIdx.x, tyd = threadIdx.y;
#pragma unroll
    for (int r = 0; r < 4; r++) {
        int n = nb + tyd + r * 8;
        tile[tyd + r * 8][txd] = (n < COUT2) ? w[(size_t)n * K2 + kb + txd] : 0.0f;
    }
    __syncthreads();
    int n = nb + txd;
#pragma unroll
    for (int r = 0; r < 4; r++) {
        int k = kb + tyd + r * 8;
        unsigned short h, l;
        split_bf16(tile[txd][tyd + r * 8], h, l);
        g_w2hi[(size_t)k * N2PAD + n] = __ushort_as_bfloat16(h);
        g_w2lo[(size_t)k * N2PAD + n] = __ushort_as_bfloat16(l);
    }
}

// ---------------------------------------------------------------------------
// im2col: feat [B][C][32][32] fp32 -> g_ahi/g_alo [k][m] bf16 (zero-padded 3x3)
// One thread: one k, 8 consecutive m (same image row; x multiple of 8).
// ---------------------------------------------------------------------------
__global__ __launch_bounds__(256)
void k_im2col(const float* __restrict__ feat) {
    int k = blockIdx.y;
    int c = k / 9;
    int q = k - 9 * c;
    int r = q / 3;
    int s = q - 3 * r;
    int m8 = (blockIdx.x * 256 + threadIdx.x) * 8;
    int img = m8 >> 10;
    int pos = m8 & 1023;
    int y = pos >> 5, x = pos & 31;
    int iy = y + r - 1;
    bool rowok = (unsigned)iy < 32u;
    const float* row = feat + (((size_t)img * CIN + c) << 10) + (iy << 5);
    uint4 hv, lv;
    unsigned short* hp = (unsigned short*)&hv;
    unsigned short* lp = (unsigned short*)&lv;
#pragma unroll
    for (int t = 0; t < 8; t++) {
        int ix = x + s - 1 + t;
        float v = (rowok && (unsigned)ix < 32u) ? row[ix] : 0.0f;
        split_bf16(v, hp[t], lp[t]);
    }
    size_t o = (size_t)k * MTOT + m8;
    *(uint4*)(g_ahi + o) = hv;
    *(uint4*)(g_alo + o) = lv;
}

// ---------------------------------------------------------------------------
// Conv1: wmma bf16x3 GEMM from precomputed im2col. CTA 128x128, 256 thr,
// warp 64x32 (wm 2 x 64m, wn 4 x 32n), KC=32, 2-stage cp.async, 2 CTAs/SM.
// blockIdx.x = n-tile (fastest -> B tiles L2-resident, A L2-shared by 8).
// ---------------------------------------------------------------------------
__global__ __launch_bounds__(256, 2)
void k_conv1_wm(const float* __restrict__ gma, const float* __restrict__ bet,
                const float* __restrict__ mea, const float* __restrict__ var) {
    extern __shared__ __align__(16) char smraw[];
    __nv_bfloat16* smb = (__nv_bfloat16*)smraw;
    float* smf = (float*)smraw;

    const int tid = threadIdx.x;
    const int w = tid >> 5;
    const int wm = w & 1, wn = w >> 1;
    const int n0 = blockIdx.x * 128;
    const int m0 = blockIdx.y * 128;

    // A cp.async: 8 threads per k-row, 16 m (two 16B chunks) each
    const int akr = tid >> 3;            // 0..31
    const int aseg = (tid & 7) * 16;
    // B cp.async: 2 threads per n-row, 16 k (two 16B chunks) each
    const int brow = tid >> 1;           // 0..127
    const int bq = (tid & 1) * 16;

    wmma::fragment<wmma::accumulator, 16, 16, 16, float> acc[4][2];
#pragma unroll
    for (int i = 0; i < 4; i++)
#pragma unroll
        for (int j = 0; j < 2; j++) wmma::fill_fragment(acc[i][j], 0.0f);

    auto loadStage = [&](int st, int kc) {
        __nv_bfloat16* base = smb + st * C1_STAGE;
        size_t ga = (size_t)(kc + akr) * MTOT + m0 + aseg;
        cp16(base + C1_AHI + akr * C1_PM + aseg,     g_ahi + ga);
        cp16(base + C1_AHI + akr * C1_PM + aseg + 8, g_ahi + ga + 8);
        cp16(base + C1_ALO + akr * C1_PM + aseg,     g_alo + ga);
        cp16(base + C1_ALO + akr * C1_PM + aseg + 8, g_alo + ga + 8);
        size_t gb = (size_t)(n0 + brow) * K1 + kc + bq;
        cp16(base + C1_BHI + brow * C1_PK + bq,     g_w1hi + gb);
        cp16(base + C1_BHI + brow * C1_PK + bq + 8, g_w1hi + gb + 8);
        cp16(base + C1_BLO + brow * C1_PK + bq,     g_w1lo + gb);
        cp16(base + C1_BLO + brow * C1_PK + bq + 8, g_w1lo + gb + 8);
    };

    auto compute = [&](int st) {
        const __nv_bfloat16* base = smb + st * C1_STAGE;
#pragma unroll
        for (int kk = 0; kk < KC; kk += 16) {
            wmma::fragment<wmma::matrix_a, 16, 16, 16, __nv_bfloat16, wmma::col_major> af[4];
            wmma::fragment<wmma::matrix_b, 16, 16, 16, __nv_bfloat16, wmma::col_major> bhf[2], blf[2];
#pragma unroll
            for (int i = 0; i < 4; i++)
                wmma::load_matrix_sync(af[i], base + C1_AHI + kk * C1_PM + wm * 64 + i * 16, C1_PM);
#pragma unroll
            for (int j = 0; j < 2; j++)
                wmma::load_matrix_sync(bhf[j], base + C1_BHI + (wn * 32 + j * 16) * C1_PK + kk, C1_PK);
#pragma unroll
            for (int i = 0; i < 4; i++)
#pragma unroll
                for (int j = 0; j < 2; j++)
                    wmma::mma_sync(acc[i][j], af[i], bhf[j], acc[i][j]);
#pragma unroll
            for (int j = 0; j < 2; j++)
                wmma::load_matrix_sync(blf[j], base + C1_BLO + (wn * 32 + j * 16) * C1_PK + kk, C1_PK);
#pragma unroll
            for (int i = 0; i < 4; i++)
#pragma unroll
                for (int j = 0; j < 2; j++)
                    wmma::mma_sync(acc[i][j], af[i], blf[j], acc[i][j]);
#pragma unroll
            for (int i = 0; i < 4; i++)
                wmma::load_matrix_sync(af[i], base + C1_ALO + kk * C1_PM + wm * 64 + i * 16, C1_PM);
#pragma unroll
            for (int i = 0; i < 4; i++)
#pragma unroll
                for (int j = 0; j < 2; j++)
                    wmma::mma_sync(acc[i][j], af[i], bhf[j], acc[i][j]);
        }
    };

    loadStage(0, 0);
    cp_commit();
    for (int kt = 0; kt < NKT1; kt++) {
        cp_wait<0>();
        __syncthreads();
        if (kt + 1 < NKT1) {
            loadStage((kt + 1) & 1, (kt + 1) * KC);
            cp_commit();
        }
        compute(kt & 1);
    }

    // Epilogue: acc -> smem col-major (element (m,n) at smf[n*128+m])
    __syncthreads();
#pragma unroll
    for (int i = 0; i < 4; i++)
#pragma unroll
        for (int j = 0; j < 2; j++)
            wmma::store_matrix_sync(smf + (wn * 32 + j * 16) * 128 + wm * 64 + i * 16,
                                    acc[i][j], 128, wmma::mem_col_major);
    __syncthreads();

    // BN + leaky, split to bf16 hi/lo, store [k][m]
#pragma unroll
    for (int it = 0; it < 16; it++) {
        int id = it * 256 + tid;
        int ncol = id >> 5;           // 0..127
        int r4 = (id & 31) * 4;       // 0..124
        float4 v = *(const float4*)(smf + ncol * 128 + r4);
        int n = n0 + ncol;
        float scale = gma[n] * rsqrtf(var[n] + 1e-5f);
        float bias = bet[n] - mea[n] * scale;
        float t;
        unsigned short h[4], l[4];
        t = v.x + bias; t = t > 0.f ? t : 0.1f * t; split_bf16(t, h[0], l[0]);
        t = v.y + bias; t = t > 0.f ? t : 0.1f * t; split_bf16(t, h[1], l[1]);
        t = v.z + bias; t = t > 0.f ? t : 0.1f * t; split_bf16(t, h[2], l[2]);
        t = v.w + bias; t = t > 0.f ? t : 0.1f * t; split_bf16(t, h[3], l[3]);
        size_t go = (size_t)n * MTOT + m0 + r4;
        *(uint2*)(g_xhi + go) = *(const uint2*)h;
        *(uint2*)(g_xlo + go) = *(const uint2*)l;
    }
}

// ---------------------------------------------------------------------------
// Conv2: wmma bf16x3 GEMM. CTA 128x128, 256 thr, warp 64x32, KC=32, 2-stage.
// blockIdx.x = n-tile (fastest -> A tiles L2-shared by 4).
// ---------------------------------------------------------------------------
__global__ __launch_bounds__(256, 2)
void k_conv2_wm(const float* __restrict__ bias2) {
    extern __shared__ __align__(16) char smraw[];
    __nv_bfloat16* smb = (__nv_bfloat16*)smraw;
    float* smf = (float*)smraw;

    const int tid = threadIdx.x;
    const int w = tid >> 5;
    const int wm = w & 1, wn = w >> 1;
    const int n0 = blockIdx.x * 128;
    const int m0 = blockIdx.y * 128;

    const int akr = tid >> 3;            // 0..31
    const int aseg = (tid & 7) * 16;
    const int bkr = tid >> 3;
    const int bseg = (tid & 7) * 16;

    wmma::fragment<wmma::accumulator, 16, 16, 16, float> acc[4][2];
#pragma unroll
    for (int i = 0; i < 4; i++)
#pragma unroll
        for (int j = 0; j < 2; j++) wmma::fill_fragment(acc[i][j], 0.0f);

    auto loadStage = [&](int st, int kc) {
        __nv_bfloat16* base = smb + st * C2_STAGE;
        size_t ga = (size_t)(kc + akr) * MTOT + m0 + aseg;
        cp16(base + C2_AHI + akr * C2_SAM + aseg,     g_xhi + ga);
        cp16(base + C2_AHI + akr * C2_SAM + aseg + 8, g_xhi + ga + 8);
        cp16(base + C2_ALO + akr * C2_SAM + aseg,     g_xlo + ga);
        cp16(base + C2_ALO + akr * C2_SAM + aseg + 8, g_xlo + ga + 8);
        size_t gb = (size_t)(kc + bkr) * N2PAD + n0 + bseg;
        cp16(base + C2_BHI + bkr * C2_SBN + bseg,     g_w2hi + gb);
        cp16(base + C2_BHI + bkr * C2_SBN + bseg + 8, g_w2hi + gb + 8);
        cp16(base + C2_BLO + bkr * C2_SBN + bseg,     g_w2lo + gb);
        cp16(base + C2_BLO + bkr * C2_SBN + bseg + 8, g_w2lo + gb + 8);
    };

    auto compute = [&](int st) {
        const __nv_bfloat16* base = smb + st * C2_STAGE;
#pragma unroll
        for (int kk = 0; kk < KC; kk += 16) {
            wmma::fragment<wmma::matrix_a, 16, 16, 16, __nv_bfloat16, wmma::col_major> af[4];
            wmma::fragment<wmma::matrix_b, 16, 16, 16, __nv_bfloat16, wmma::row_major> bhf[2], blf[2];
#pragma unroll
            for (int i = 0; i < 4; i++)
                wmma::load_matrix_sync(af[i], base + C2_AHI + kk * C2_SAM + wm * 64 + i * 16, C2_SAM);
#pragma unroll
            for (int j = 0; j < 2; j++)
                wmma::load_matrix_sync(bhf[j], base + C2_BHI + kk * C2_SBN + wn * 32 + j * 16, C2_SBN);
#pragma unroll
            for (int i = 0; i < 4; i++)
#pragma unroll
                for (int j = 0; j < 2; j++)
                    wmma::mma_sync(acc[i][j], af[i], bhf[j], acc[i][j]);
#pragma unroll
            for (int j = 0; j < 2; j++)
                wmma::load_matrix_sync(blf[j], base + C2_BLO + kk * C2_SBN + wn * 32 + j * 16, C2_SBN);
#pragma unroll
            for (int i = 0; i < 4; i++)
#pragma unroll
                for (int j = 0; j < 2; j++)
                    wmma::mma_sync(acc[i][j], af[i], blf[j], acc[i][j]);
#pragma unroll
            for (int i = 0; i < 4; i++)
                wmma::load_matrix_sync(af[i], base + C2_ALO + kk * C2_SAM + wm * 64 + i * 16, C2_SAM);
#pragma unroll
            for (int i = 0; i < 4; i++)
#pragma unroll
                for (int j = 0; j < 2; j++)
                    wmma::mma_sync(acc[i][j], af[i], bhf[j], acc[i][j]);
        }
    };

    loadStage(0, 0);
    cp_commit();
    for (int kt = 0; kt < NKT2; kt++) {
        cp_wait<0>();
        __syncthreads();
        if (kt + 1 < NKT2) {
            loadStage((kt + 1) & 1, (kt + 1) * KC);
            cp_commit();
        }
        compute(kt & 1);
    }

    // Epilogue: acc -> smem row-major (element (m,n) at smf[m*128+n]), + bias -> g_p
    __syncthreads();
#pragma unroll
    for (int i = 0; i < 4; i++)
#pragma unroll
        for (int j = 0; j < 2; j++)
            wmma::store_matrix_sync(smf + (wm * 64 + i * 16) * 128 + wn * 32 + j * 16,
                                    acc[i][j], 128, wmma::mem_row_major);
    __syncthreads();

#pragma unroll
    for (int it = 0; it < 16; it++) {
        int id = it * 256 + tid;
        int mrow = id >> 5;          // 0..127
        int nc4 = (id & 31) * 4;
        float4 v = *(const float4*)(smf + mrow * 128 + nc4);
        int n = n0 + nc4;
        float* dst = g_p + (size_t)(m0 + mrow) * COUT2 + n;
        if (n + 0 < COUT2) dst[0] = v.x + bias2[n + 0];
        if (n + 1 < COUT2) dst[1] = v.y + bias2[n + 1];
        if (n + 2 < COUT2) dst[2] = v.z + bias2[n + 2];
        if (n + 3 < COUT2) dst[3] = v.w + bias2[n + 3];
    }
}

// ---------------------------------------------------------------------------
// Decode: one warp per (position, anchor)
// ---------------------------------------------------------------------------
__global__ void k_decode(float* __restrict__ out) {
    int g = blockIdx.x * (blockDim.x >> 5) + (threadIdx.x >> 5);
    int lane = threadIdx.x & 31;
    if (g >= MTOT * 5) return;
    int m = g / 5;
    int a = g - m * 5;
    const float* base = g_p + (size_t)m * COUT2 + a * 85;

    float t0 = base[0], t1 = base[1], t2 = base[2], t3 = base[3], t4 = base[4];

    float l0 = base[5 + lane];
    float l1 = base[5 + 32 + lane];
    float best = l0; int bi = lane;
    if (l1 > best) { best = l1; bi = lane + 32; }
    float l2 = -3.4e38f;
    if (lane < 16) {
        l2 = base[5 + 64 + lane];
        if (l2 > best) { best = l2; bi = lane + 64; }
    }
#pragma unroll
    for (int off = 16; off; off >>= 1) {
        float ob = __shfl_down_sync(0xffffffffu, best, off);
        int   oi = __shfl_down_sync(0xffffffffu, bi, off);
        if (ob > best || (ob == best && oi < bi)) { best = ob; bi = oi; }
    }
    float mx = __shfl_sync(0xffffffffu, best, 0);
    int gidx = __shfl_sync(0xffffffffu, bi, 0);

    float s = expf(l0 - mx) + expf(l1 - mx) + ((lane < 16) ? expf(l2 - mx) : 0.f);
#pragma unroll
    for (int off = 16; off; off >>= 1)
        s += __shfl_down_sync(0xffffffffu, s, off);

    if (lane == 0) {
        float bx = 1.f / (1.f + expf(-t0));
        float by = 1.f / (1.f + expf(-t1));
        float bw = expf(fminf(t2, 8.f));
        float bh = expf(fminf(t3, 8.f));
        float obj = 1.f / (1.f + expf(-t4));
        float score = obj / s;

        int b = m >> 10;
        int pos = m & 1023;
        int gy = pos >> 5, gx = pos & 31;
        float cx = (bx + (float)gx) * 32.f;
        float cy = (by + (float)gy) * 32.f;
        float pw = c_anc_w[a] * bw;
        float ph = c_anc_h[a] * bh;
        float x1 = fminf(fmaxf(cx - 0.5f * pw, 0.f), 1023.f);
        float y1 = fminf(fmaxf(cy - 0.5f * ph, 0.f), 1023.f);
        float x2 = fminf(fmaxf(cx + 0.5f * pw, 0.f), 1023.f);
        float y2 = fminf(fmaxf(cy + 0.5f * ph, 0.f), 1023.f);

        int idxo = pos * 5 + a;
        float* o5 = out + ((size_t)b * 5120 + idxo) * 5;
        o5[0] = x1; o5[1] = y1; o5[2] = x2; o5[3] = y2; o5[4] = score;
        out[(size_t)NBATCH * 5120 * 5 + (size_t)b * 5120 + idxo] = (float)gidx;
    }
}

// ---------------------------------------------------------------------------
extern "C" void kernel_launch(void* const* d_in, const int* in_sizes, int n_in,
                              void* d_out, int out_size) {
    const float* feat = (const float*)d_in[0];
    const float* w1   = (const float*)d_in[1];
    const float* gma  = (const float*)d_in[2];
    const float* bet  = (const float*)d_in[3];
    const float* mea  = (const float*)d_in[4];
    const float* var  = (const float*)d_in[5];
    const float* w2   = (const float*)d_in[6];
    const float* b2   = (const float*)d_in[7];
    float* out = (float*)d_out;

    static int attr_set = 0;
    if (!attr_set) {
        cudaFuncSetAttribute(k_conv1_wm, cudaFuncAttributeMaxDynamicSharedMemorySize, C1_SMEM_B);
        cudaFuncSetAttribute(k_conv2_wm, cudaFuncAttributeMaxDynamicSharedMemorySize, C2_SMEM_B);
        attr_set = 1;
    }

    k_split_w1<<<(COUT1 * K1 + 255) / 256, 256>>>(w1, gma, var);
    k_split_w2<<<dim3(K2 / 32, N2PAD / 32), dim3(32, 8)>>>(w2);
    k_im2col<<<dim3(MTOT / (8 * 256), K1), 256>>>(feat);
    k_conv1_wm<<<dim3(COUT1 / 128, MTOT / 128), 256, C1_SMEM_B>>>(gma, bet, mea, var);
    k_conv2_wm<<<dim3(N2PAD / 128, MTOT / 128), 256, C2_SMEM_B>>>(b2);
    k_decode<<<(MTOT * 5 * 32 + 255) / 256, 256>>>(out);
}